// round 1
// baseline (speedup 1.0000x reference)
#include <cuda_runtime.h>
#include <math.h>

#define B 2
#define S 2048
#define H 1024
#define NH 16
#define HD 64
#define BH 4
#define BD 256
#define MS (B*S)   /* 4096 rows */

// ---------------- scratch (static device globals; no allocations) ----------------
__device__ float g_Q[MS * H];
__device__ float g_K[MS * H];
__device__ float g_V[MS * H];
__device__ float g_MOD[MS * NH];
__device__ float g_CTX[MS * H];
__device__ float g_QKV3[MS * 3 * H];
__device__ float g_T1[MS * H];
__device__ float g_T2[MS * H];

// ---------------- 128x128x8 SGEMM: C = A[MxK] @ W[KxN] + bias[N] ----------------
__global__ __launch_bounds__(256) void sgemm128(
    const float* __restrict__ A, const float* __restrict__ W,
    const float* __restrict__ bias, float* __restrict__ C,
    int M, int N, int K)
{
    __shared__ float As[8][128];
    __shared__ float Bs[8][128];
    int tid = threadIdx.x;
    int m0 = blockIdx.y * 128, n0 = blockIdx.x * 128;
    int tx = tid & 15, ty = tid >> 4;

    float acc[8][8];
#pragma unroll
    for (int i = 0; i < 8; i++)
#pragma unroll
        for (int j = 0; j < 8; j++) acc[i][j] = 0.f;

    int ar = tid >> 1, ac4 = (tid & 1) * 4;
    int br = tid >> 5, bc4 = (tid & 31) * 4;
    const float* Aptr = A + (size_t)(m0 + ar) * K + ac4;
    const float* Bptr = W + (size_t)br * N + n0 + bc4;

    for (int kt = 0; kt < K; kt += 8) {
        float4 av = *(const float4*)(Aptr + kt);
        As[ac4 + 0][ar] = av.x; As[ac4 + 1][ar] = av.y;
        As[ac4 + 2][ar] = av.z; As[ac4 + 3][ar] = av.w;
        float4 bv = *(const float4*)(Bptr + (size_t)kt * N);
        *(float4*)&Bs[br][bc4] = bv;
        __syncthreads();
#pragma unroll
        for (int k = 0; k < 8; k++) {
            float4 a0 = *(const float4*)&As[k][ty * 8];
            float4 a1 = *(const float4*)&As[k][ty * 8 + 4];
            float4 b0 = *(const float4*)&Bs[k][tx * 8];
            float4 b1 = *(const float4*)&Bs[k][tx * 8 + 4];
            float ra[8] = {a0.x, a0.y, a0.z, a0.w, a1.x, a1.y, a1.z, a1.w};
            float rb[8] = {b0.x, b0.y, b0.z, b0.w, b1.x, b1.y, b1.z, b1.w};
#pragma unroll
            for (int i = 0; i < 8; i++)
#pragma unroll
                for (int j = 0; j < 8; j++) acc[i][j] += ra[i] * rb[j];
        }
        __syncthreads();
    }
#pragma unroll
    for (int i = 0; i < 8; i++) {
        size_t row = (size_t)(m0 + ty * 8 + i) * N;
        int col = n0 + tx * 8;
        float4 o0, o1;
        o0.x = acc[i][0] + bias[col + 0]; o0.y = acc[i][1] + bias[col + 1];
        o0.z = acc[i][2] + bias[col + 2]; o0.w = acc[i][3] + bias[col + 3];
        o1.x = acc[i][4] + bias[col + 4]; o1.y = acc[i][5] + bias[col + 5];
        o1.z = acc[i][6] + bias[col + 6]; o1.w = acc[i][7] + bias[col + 7];
        *(float4*)(C + row + col) = o0;
        *(float4*)(C + row + col + 4) = o1;
    }
}

// ---------------- modulation: sigmoid(hs@Wg + bg + cvec@Wa + ba) ----------------
__global__ __launch_bounds__(256) void gatemod(
    const float* __restrict__ hs, const float* __restrict__ Wg,
    const float* __restrict__ bg, const float* __restrict__ cvec,
    const float* __restrict__ Wa, const float* __restrict__ ba,
    float* __restrict__ MODo)
{
    int t = blockIdx.x * 256 + threadIdx.x;           // 0..MS*NH-1
    int m = t >> 4, n = t & 15;
    const float* row = hs + (size_t)m * H;
    float s = 0.f;
    for (int k = 0; k < H; k++) s += row[k] * Wg[k * NH + n];
    float aw = ba[n];
#pragma unroll
    for (int k = 0; k < 16; k++) aw += cvec[k] * Wa[k * 16 + n];
    float x = s + bg[n] + aw;
    MODo[t] = 1.f / (1.f + __expf(-x));
}

// ---------------- main attention: 16 heads, hd=64, modulated scores, mask ----------------
__global__ __launch_bounds__(256) void attn_main(
    const float* __restrict__ Qb, const float* __restrict__ Kb,
    const float* __restrict__ Vb, const float* __restrict__ MODb,
    const int* __restrict__ maskb, float* __restrict__ Ob)
{
    __shared__ float QsT[64][32];     // Q transposed [d][q]
    __shared__ float KV[64][64];      // K^T [d][k] then V [k][d]
    __shared__ float Ss[32][64];
    __shared__ float Ps[64][33];      // P transposed [k][q]
    __shared__ float Msc[32], Mst[32], Lst[32], Alp[32], Madd[64];

    const float NEGINF = __int_as_float(0xff800000);
    int tid = threadIdx.x, lane = tid & 31, warp = tid >> 5;
    int qt = blockIdx.x, h = blockIdx.y, b = blockIdx.z;
    int q0 = qt * 32;

    const float* Qg = Qb + (size_t)(b * S + q0) * H + h * HD;
    for (int i = tid; i < 512; i += 256) {
        int q = i >> 4, c4 = (i & 15) * 4;
        float4 v = *(const float4*)(Qg + (size_t)q * H + c4);
        QsT[c4 + 0][q] = v.x; QsT[c4 + 1][q] = v.y;
        QsT[c4 + 2][q] = v.z; QsT[c4 + 3][q] = v.w;
    }
    if (tid < 32) {
        Msc[tid] = MODb[(size_t)(b * S + q0 + tid) * NH + h] * 0.125f;
        Mst[tid] = NEGINF; Lst[tid] = 0.f;
    }
    int tx = tid & 15, ty = tid >> 4;
    float acc[2][4];
#pragma unroll
    for (int i = 0; i < 2; i++)
#pragma unroll
        for (int j = 0; j < 4; j++) acc[i][j] = 0.f;

    for (int kt = 0; kt < S; kt += 64) {
        __syncthreads();
        const float* Kg = Kb + (size_t)(b * S + kt) * H + h * HD;
        for (int i = tid; i < 1024; i += 256) {
            int r = i >> 4, c4 = (i & 15) * 4;
            float4 v = *(const float4*)(Kg + (size_t)r * H + c4);
            KV[c4 + 0][r] = v.x; KV[c4 + 1][r] = v.y;
            KV[c4 + 2][r] = v.z; KV[c4 + 3][r] = v.w;
        }
        if (tid < 64) Madd[tid] = (maskb[b * S + kt + tid] == 0) ? NEGINF : 0.f;
        __syncthreads();

        // scores: q = ty*2+{0,1}, k = tx*4+j
        float sc[2][4];
#pragma unroll
        for (int i = 0; i < 2; i++)
#pragma unroll
            for (int j = 0; j < 4; j++) sc[i][j] = 0.f;
#pragma unroll 16
        for (int d = 0; d < 64; d++) {
            float qv0 = QsT[d][ty * 2], qv1 = QsT[d][ty * 2 + 1];
            float4 kv = *(const float4*)&KV[d][tx * 4];
            sc[0][0] += qv0 * kv.x; sc[0][1] += qv0 * kv.y;
            sc[0][2] += qv0 * kv.z; sc[0][3] += qv0 * kv.w;
            sc[1][0] += qv1 * kv.x; sc[1][1] += qv1 * kv.y;
            sc[1][2] += qv1 * kv.z; sc[1][3] += qv1 * kv.w;
        }
#pragma unroll
        for (int i = 0; i < 2; i++) {
            float mm = Msc[ty * 2 + i];
#pragma unroll
            for (int j = 0; j < 4; j++)
                Ss[ty * 2 + i][tx * 4 + j] = sc[i][j] * mm + Madd[tx * 4 + j];
        }
        __syncthreads();

        // online softmax: warp handles 4 query rows
#pragma unroll
        for (int r = 0; r < 4; r++) {
            int q = warp * 4 + r;
            float s0 = Ss[q][lane], s1 = Ss[q][lane + 32];
            float mx = fmaxf(s0, s1);
#pragma unroll
            for (int o = 16; o > 0; o >>= 1)
                mx = fmaxf(mx, __shfl_xor_sync(0xffffffffu, mx, o));
            float mold = Mst[q];
            float mnew = fmaxf(mold, mx);
            float p0, p1, al;
            if (mnew == NEGINF) { p0 = 0.f; p1 = 0.f; al = 1.f; }
            else {
                p0 = __expf(s0 - mnew); p1 = __expf(s1 - mnew);
                al = (mold == NEGINF) ? 0.f : __expf(mold - mnew);
            }
            float ps = p0 + p1;
#pragma unroll
            for (int o = 16; o > 0; o >>= 1)
                ps += __shfl_xor_sync(0xffffffffu, ps, o);
            if (lane == 0) { Mst[q] = mnew; Lst[q] = Lst[q] * al + ps; Alp[q] = al; }
            Ps[lane][q] = p0; Ps[lane + 32][q] = p1;
        }
        __syncthreads();

        // load V into KV as [k][d]
        const float* Vg = Vb + (size_t)(b * S + kt) * H + h * HD;
        for (int i = tid; i < 1024; i += 256) {
            int r = i >> 4, c4 = (i & 15) * 4;
            *(float4*)&KV[r][c4] = *(const float4*)(Vg + (size_t)r * H + c4);
        }
        __syncthreads();

        float a0 = Alp[ty * 2], a1 = Alp[ty * 2 + 1];
#pragma unroll
        for (int j = 0; j < 4; j++) { acc[0][j] *= a0; acc[1][j] *= a1; }
#pragma unroll 16
        for (int k = 0; k < 64; k++) {
            float p0v = Ps[k][ty * 2], p1v = Ps[k][ty * 2 + 1];
            float4 vv = *(const float4*)&KV[k][tx * 4];
            acc[0][0] += p0v * vv.x; acc[0][1] += p0v * vv.y;
            acc[0][2] += p0v * vv.z; acc[0][3] += p0v * vv.w;
            acc[1][0] += p1v * vv.x; acc[1][1] += p1v * vv.y;
            acc[1][2] += p1v * vv.z; acc[1][3] += p1v * vv.w;
        }
    }
    __syncthreads();
    float* Og = Ob + (size_t)(b * S + q0) * H + h * HD;
#pragma unroll
    for (int i = 0; i < 2; i++) {
        float inv = 1.f / Lst[ty * 2 + i];
        float4 o;
        o.x = acc[i][0] * inv; o.y = acc[i][1] * inv;
        o.z = acc[i][2] * inv; o.w = acc[i][3] * inv;
        *(float4*)(Og + (size_t)(ty * 2 + i) * H + tx * 4) = o;
    }
}

// ---------------- big-head attention: 4 heads, hd=256 (causal & meta MHA) ----------------
__global__ __launch_bounds__(256) void attn_big(
    const float* __restrict__ Qb, const float* __restrict__ Kb,
    const float* __restrict__ Vb, int ld, float* __restrict__ Ob, float scale)
{
    __shared__ float QsT[256][16];    // Q transposed [d][q], full depth
    __shared__ float KV[64][64];      // K^T chunk [d][k] / V chunk [k][d]
    __shared__ float Ss[16][64];
    __shared__ float Ps[64][17];
    __shared__ float Mst[16], Lst[16], Alp[16];

    const float NEGINF = __int_as_float(0xff800000);
    int tid = threadIdx.x, lane = tid & 31, warp = tid >> 5;
    int qt = blockIdx.x, h = blockIdx.y, b = blockIdx.z;
    int q0 = qt * 16;

    const float* Qg = Qb + (size_t)(b * S + q0) * ld + h * BD;
    for (int i = tid; i < 1024; i += 256) {
        int q = i >> 6, c4 = (i & 63) * 4;
        float4 v = *(const float4*)(Qg + (size_t)q * ld + c4);
        QsT[c4 + 0][q] = v.x; QsT[c4 + 1][q] = v.y;
        QsT[c4 + 2][q] = v.z; QsT[c4 + 3][q] = v.w;
    }
    if (tid < 16) { Mst[tid] = NEGINF; Lst[tid] = 0.f; }

    int tx = tid & 15, ty = tid >> 4;   // score: q=ty, k=tx*4+j ; PV: q=ty, d=ch*64+tx*4+j
    float acc[4][4];
#pragma unroll
    for (int c = 0; c < 4; c++)
#pragma unroll
        for (int j = 0; j < 4; j++) acc[c][j] = 0.f;

    for (int kt = 0; kt < S; kt += 64) {
        float sc[4] = {0.f, 0.f, 0.f, 0.f};
        const float* Kg = Kb + (size_t)(b * S + kt) * ld + h * BD;
#pragma unroll
        for (int ch = 0; ch < 4; ch++) {
            __syncthreads();
            for (int i = tid; i < 1024; i += 256) {
                int r = i >> 4, c4 = (i & 15) * 4;
                float4 v = *(const float4*)(Kg + (size_t)r * ld + ch * 64 + c4);
                KV[c4 + 0][r] = v.x; KV[c4 + 1][r] = v.y;
                KV[c4 + 2][r] = v.z; KV[c4 + 3][r] = v.w;
            }
            __syncthreads();
#pragma unroll 16
            for (int d = 0; d < 64; d++) {
                float qv = QsT[ch * 64 + d][ty];
                float4 kv = *(const float4*)&KV[d][tx * 4];
                sc[0] += qv * kv.x; sc[1] += qv * kv.y;
                sc[2] += qv * kv.z; sc[3] += qv * kv.w;
            }
        }
#pragma unroll
        for (int j = 0; j < 4; j++) Ss[ty][tx * 4 + j] = sc[j] * scale;
        __syncthreads();

#pragma unroll
        for (int r = 0; r < 2; r++) {
            int q = warp * 2 + r;
            float s0 = Ss[q][lane], s1 = Ss[q][lane + 32];
            float mx = fmaxf(s0, s1);
#pragma unroll
            for (int o = 16; o > 0; o >>= 1)
                mx = fmaxf(mx, __shfl_xor_sync(0xffffffffu, mx, o));
            float mold = Mst[q];
            float mnew = fmaxf(mold, mx);
            float p0 = __expf(s0 - mnew), p1 = __expf(s1 - mnew);
            float al = (mold == NEGINF) ? 0.f : __expf(mold - mnew);
            float ps = p0 + p1;
#pragma unroll
            for (int o = 16; o > 0; o >>= 1)
                ps += __shfl_xor_sync(0xffffffffu, ps, o);
            if (lane == 0) { Mst[q] = mnew; Lst[q] = Lst[q] * al + ps; Alp[q] = al; }
            Ps[lane][q] = p0; Ps[lane + 32][q] = p1;
        }
        __syncthreads();

        float al = Alp[ty];
#pragma unroll
        for (int c = 0; c < 4; c++)
#pragma unroll
            for (int j = 0; j < 4; j++) acc[c][j] *= al;

        const float* Vg = Vb + (size_t)(b * S + kt) * ld + h * BD;
#pragma unroll
        for (int ch = 0; ch < 4; ch++) {
            __syncthreads();
            for (int i = tid; i < 1024; i += 256) {
                int r = i >> 4, c4 = (i & 15) * 4;
                *(float4*)&KV[r][c4] = *(const float4*)(Vg + (size_t)r * ld + ch * 64 + c4);
            }
            __syncthreads();
#pragma unroll 16
            for (int k = 0; k < 64; k++) {
                float pv = Ps[k][ty];
                float4 vv = *(const float4*)&KV[k][tx * 4];
                acc[ch][0] += pv * vv.x; acc[ch][1] += pv * vv.y;
                acc[ch][2] += pv * vv.z; acc[ch][3] += pv * vv.w;
            }
        }
    }
    __syncthreads();
    float inv = 1.f / Lst[ty];
    float* Og = Ob + (size_t)(b * S + q0 + ty) * H + h * BD;
#pragma unroll
    for (int ch = 0; ch < 4; ch++) {
        float4 o;
        o.x = acc[ch][0] * inv; o.y = acc[ch][1] * inv;
        o.z = acc[ch][2] * inv; o.w = acc[ch][3] * inv;
        *(float4*)(Og + ch * 64 + tx * 4) = o;
    }
}

// ---------------- elementwise blend: dst = a*wa + b*wb ----------------
__global__ __launch_bounds__(256) void blend(
    float* __restrict__ dst, const float* __restrict__ a,
    const float* __restrict__ bsrc, float wa, float wb, int n)
{
    int i = blockIdx.x * 256 + threadIdx.x;
    if (i < n) dst[i] = a[i] * wa + bsrc[i] * wb;
}

// ---------------- launch ----------------
extern "C" void kernel_launch(void* const* d_in, const int* in_sizes, int n_in,
                              void* d_out, int out_size)
{
    (void)in_sizes; (void)n_in; (void)out_size;
    const float* hs      = (const float*)d_in[0];
    const int*   mask    = (const int*)  d_in[1];
    const float* cvec    = (const float*)d_in[2];
    const float* Wq      = (const float*)d_in[3];
    const float* bq      = (const float*)d_in[4];
    const float* Wk      = (const float*)d_in[5];
    const float* bk      = (const float*)d_in[6];
    const float* Wv      = (const float*)d_in[7];
    const float* bv      = (const float*)d_in[8];
    const float* Wg      = (const float*)d_in[9];
    const float* bg      = (const float*)d_in[10];
    const float* Wa      = (const float*)d_in[11];
    const float* ba      = (const float*)d_in[12];
    const float* ca_in_w = (const float*)d_in[13];
    const float* ca_in_b = (const float*)d_in[14];
    const float* ca_ow   = (const float*)d_in[15];
    const float* ca_ob   = (const float*)d_in[16];
    const float* ma_in_w = (const float*)d_in[17];
    const float* ma_in_b = (const float*)d_in[18];
    const float* ma_ow   = (const float*)d_in[19];
    const float* ma_ob   = (const float*)d_in[20];
    const float* Wo      = (const float*)d_in[21];
    const float* bo      = (const float*)d_in[22];

    float *Q, *K, *V, *MOD, *CTX, *QKV3, *T1, *T2;
    cudaGetSymbolAddress((void**)&Q, g_Q);
    cudaGetSymbolAddress((void**)&K, g_K);
    cudaGetSymbolAddress((void**)&V, g_V);
    cudaGetSymbolAddress((void**)&MOD, g_MOD);
    cudaGetSymbolAddress((void**)&CTX, g_CTX);
    cudaGetSymbolAddress((void**)&QKV3, g_QKV3);
    cudaGetSymbolAddress((void**)&T1, g_T1);
    cudaGetSymbolAddress((void**)&T2, g_T2);

    dim3 gN1(H / 128, MS / 128);          // 8 x 32
    dim3 gN3(3 * H / 128, MS / 128);      // 24 x 32

    // main attention path
    sgemm128<<<gN1, 256>>>(hs, Wq, bq, Q, MS, H, H);
    sgemm128<<<gN1, 256>>>(hs, Wk, bk, K, MS, H, H);
    sgemm128<<<gN1, 256>>>(hs, Wv, bv, V, MS, H, H);
    gatemod<<<MS * NH / 256, 256>>>(hs, Wg, bg, cvec, Wa, ba, MOD);
    attn_main<<<dim3(S / 32, NH, B), 256>>>(Q, K, V, MOD, mask, CTX);

    // causal branch
    sgemm128<<<gN3, 256>>>(hs, ca_in_w, ca_in_b, QKV3, MS, 3 * H, H);
    attn_big<<<dim3(S / 16, BH, B), 256>>>(QKV3, QKV3 + H, QKV3 + 2 * H, 3 * H, T1, 0.0625f);
    sgemm128<<<gN1, 256>>>(T1, ca_ow, ca_ob, T2, MS, H, H);
    blend<<<MS * H / 256, 256>>>(CTX, CTX, T2, 0.3f, 0.7f, MS * H);

    // metacognitive branch
    sgemm128<<<gN3, 256>>>(CTX, ma_in_w, ma_in_b, QKV3, MS, 3 * H, H);
    attn_big<<<dim3(S / 16, BH, B), 256>>>(QKV3, QKV3 + H, QKV3 + 2 * H, 3 * H, T1, 0.0625f);
    sgemm128<<<gN1, 256>>>(T1, ma_ow, ma_ob, T2, MS, H, H);
    blend<<<MS * H / 256, 256>>>(CTX, CTX, T2, 0.85f, 0.15f, MS * H);

    // output projection
    sgemm128<<<gN1, 256>>>(CTX, Wo, bo, (float*)d_out, MS, H, H);
}

// round 2
// speedup vs baseline: 1.1419x; 1.1419x over previous
#include <cuda_runtime.h>
#include <math.h>

#define B 2
#define S 2048
#define H 1024
#define NH 16
#define HD 64
#define BH 4
#define BD 256
#define MS (B*S)   /* 4096 rows */

// ---------------- scratch (static device globals; no allocations) ----------------
__device__ float g_Q[MS * H];
__device__ float g_K[MS * H];
__device__ float g_V[MS * H];
__device__ float g_MOD[MS * NH];
__device__ float g_CTX[MS * H];
__device__ float g_QKV3[MS * 3 * H];
__device__ float g_T1[MS * H];
__device__ float g_T2[MS * H];

// ---------------- TF32 tensor-core GEMM: C = A[MxK] @ W[KxN] + bias[N] ----------------
// block tile 128x128x32, 8 warps (2x4), warp tile 64x32, mma.m16n8k8.tf32
#define BM 128
#define BN 128
#define BK 32

__device__ __forceinline__ unsigned f2tf32(float f) {
    unsigned u;
    asm("cvt.rna.tf32.f32 %0, %1;" : "=r"(u) : "f"(f));
    return u;
}

__device__ __forceinline__ void mma_tf32(float* d, const unsigned* a, const unsigned* b) {
    asm volatile(
        "mma.sync.aligned.m16n8k8.row.col.f32.tf32.tf32.f32 "
        "{%0,%1,%2,%3}, {%4,%5,%6,%7}, {%8,%9}, {%0,%1,%2,%3};"
        : "+f"(d[0]), "+f"(d[1]), "+f"(d[2]), "+f"(d[3])
        : "r"(a[0]), "r"(a[1]), "r"(a[2]), "r"(a[3]), "r"(b[0]), "r"(b[1]));
}

__global__ __launch_bounds__(256) void gemm_tf32(
    const float* __restrict__ A, const float* __restrict__ W,
    const float* __restrict__ bias, float* __restrict__ C,
    int M, int N, int K)
{
    __shared__ unsigned As[BM][BK + 4];   // [128][36] pad -> conflict-free frag LDS
    __shared__ unsigned Bs[BK][BN + 4];   // [32][132]

    int tid = threadIdx.x;
    int warp = tid >> 5, lane = tid & 31;
    int gid = lane >> 2, tig = lane & 3;
    int wm = (warp >> 2) * 64;            // 0 or 64
    int wn = (warp & 3) * 32;             // 0,32,64,96
    int m0 = blockIdx.y * BM, n0 = blockIdx.x * BN;

    float acc[4][4][4];
#pragma unroll
    for (int mt = 0; mt < 4; mt++)
#pragma unroll
        for (int nt = 0; nt < 4; nt++)
#pragma unroll
            for (int r = 0; r < 4; r++) acc[mt][nt][r] = 0.f;

    int aRow[4], aCol[4], bRow[4], bCol[4];
#pragma unroll
    for (int i = 0; i < 4; i++) {
        int fi = tid + 256 * i;
        aRow[i] = fi >> 3;  aCol[i] = (fi & 7) * 4;    // A tile 128x32
        bRow[i] = fi >> 5;  bCol[i] = (fi & 31) * 4;   // B tile 32x128
    }

    float4 aReg[4], bReg[4];
#pragma unroll
    for (int i = 0; i < 4; i++) {
        aReg[i] = *(const float4*)(A + (size_t)(m0 + aRow[i]) * K + aCol[i]);
        bReg[i] = *(const float4*)(W + (size_t)bRow[i] * N + n0 + bCol[i]);
    }
#pragma unroll
    for (int i = 0; i < 4; i++) {
        As[aRow[i]][aCol[i] + 0] = f2tf32(aReg[i].x);
        As[aRow[i]][aCol[i] + 1] = f2tf32(aReg[i].y);
        As[aRow[i]][aCol[i] + 2] = f2tf32(aReg[i].z);
        As[aRow[i]][aCol[i] + 3] = f2tf32(aReg[i].w);
        uint4 bu;
        bu.x = f2tf32(bReg[i].x); bu.y = f2tf32(bReg[i].y);
        bu.z = f2tf32(bReg[i].z); bu.w = f2tf32(bReg[i].w);
        *(uint4*)&Bs[bRow[i]][bCol[i]] = bu;
    }
    __syncthreads();

    int ntiles = K / BK;
    for (int kt = 0; kt < ntiles; kt++) {
        if (kt + 1 < ntiles) {
            int kb = (kt + 1) * BK;
#pragma unroll
            for (int i = 0; i < 4; i++) {
                aReg[i] = *(const float4*)(A + (size_t)(m0 + aRow[i]) * K + kb + aCol[i]);
                bReg[i] = *(const float4*)(W + (size_t)(kb + bRow[i]) * N + n0 + bCol[i]);
            }
        }
#pragma unroll
        for (int q = 0; q < 4; q++) {
            int kq = q * 8;
            unsigned af[4][4], bf[4][2];
#pragma unroll
            for (int mt = 0; mt < 4; mt++) {
                int r = wm + mt * 16 + gid;
                af[mt][0] = As[r][kq + tig];
                af[mt][1] = As[r + 8][kq + tig];
                af[mt][2] = As[r][kq + tig + 4];
                af[mt][3] = As[r + 8][kq + tig + 4];
            }
#pragma unroll
            for (int nt = 0; nt < 4; nt++) {
                int c = wn + nt * 8 + gid;
                bf[nt][0] = Bs[kq + tig][c];
                bf[nt][1] = Bs[kq + tig + 4][c];
            }
#pragma unroll
            for (int mt = 0; mt < 4; mt++)
#pragma unroll
                for (int nt = 0; nt < 4; nt++)
                    mma_tf32(acc[mt][nt], af[mt], bf[nt]);
        }
        __syncthreads();
        if (kt + 1 < ntiles) {
#pragma unroll
            for (int i = 0; i < 4; i++) {
                As[aRow[i]][aCol[i] + 0] = f2tf32(aReg[i].x);
                As[aRow[i]][aCol[i] + 1] = f2tf32(aReg[i].y);
                As[aRow[i]][aCol[i] + 2] = f2tf32(aReg[i].z);
                As[aRow[i]][aCol[i] + 3] = f2tf32(aReg[i].w);
                uint4 bu;
                bu.x = f2tf32(bReg[i].x); bu.y = f2tf32(bReg[i].y);
                bu.z = f2tf32(bReg[i].z); bu.w = f2tf32(bReg[i].w);
                *(uint4*)&Bs[bRow[i]][bCol[i]] = bu;
            }
            __syncthreads();
        }
    }

#pragma unroll
    for (int mt = 0; mt < 4; mt++) {
        int r0 = m0 + wm + mt * 16 + gid;
#pragma unroll
        for (int nt = 0; nt < 4; nt++) {
            int c = n0 + wn + nt * 8 + tig * 2;
            float b0v = bias[c], b1v = bias[c + 1];
            float2 v0, v1;
            v0.x = acc[mt][nt][0] + b0v; v0.y = acc[mt][nt][1] + b1v;
            v1.x = acc[mt][nt][2] + b0v; v1.y = acc[mt][nt][3] + b1v;
            *(float2*)(C + (size_t)r0 * N + c) = v0;
            *(float2*)(C + (size_t)(r0 + 8) * N + c) = v1;
        }
    }
}

// ---------------- modulation: sigmoid(hs@Wg + bg + cvec@Wa + ba) ----------------
__global__ __launch_bounds__(256) void gatemod(
    const float* __restrict__ hs, const float* __restrict__ Wg,
    const float* __restrict__ bg, const float* __restrict__ cvec,
    const float* __restrict__ Wa, const float* __restrict__ ba,
    float* __restrict__ MODo)
{
    int t = blockIdx.x * 256 + threadIdx.x;           // 0..MS*NH-1
    int m = t >> 4, n = t & 15;
    const float* row = hs + (size_t)m * H;
    float s = 0.f;
    for (int k = 0; k < H; k++) s += row[k] * Wg[k * NH + n];
    float aw = ba[n];
#pragma unroll
    for (int k = 0; k < 16; k++) aw += cvec[k] * Wa[k * 16 + n];
    float x = s + bg[n] + aw;
    MODo[t] = 1.f / (1.f + __expf(-x));
}

// ---------------- main attention: 16 heads, hd=64, modulated scores, mask ----------------
__global__ __launch_bounds__(256) void attn_main(
    const float* __restrict__ Qb, const float* __restrict__ Kb,
    const float* __restrict__ Vb, const float* __restrict__ MODb,
    const int* __restrict__ maskb, float* __restrict__ Ob)
{
    __shared__ float QsT[64][32];     // Q transposed [d][q]
    __shared__ float KV[64][64];      // K^T [d][k] then V [k][d]
    __shared__ float Ss[32][64];
    __shared__ float Ps[64][33];      // P transposed [k][q]
    __shared__ float Msc[32], Mst[32], Lst[32], Alp[32], Madd[64];

    const float NEGINF = __int_as_float(0xff800000);
    int tid = threadIdx.x, lane = tid & 31, warp = tid >> 5;
    int qt = blockIdx.x, h = blockIdx.y, b = blockIdx.z;
    int q0 = qt * 32;

    const float* Qg = Qb + (size_t)(b * S + q0) * H + h * HD;
    for (int i = tid; i < 512; i += 256) {
        int q = i >> 4, c4 = (i & 15) * 4;
        float4 v = *(const float4*)(Qg + (size_t)q * H + c4);
        QsT[c4 + 0][q] = v.x; QsT[c4 + 1][q] = v.y;
        QsT[c4 + 2][q] = v.z; QsT[c4 + 3][q] = v.w;
    }
    if (tid < 32) {
        Msc[tid] = MODb[(size_t)(b * S + q0 + tid) * NH + h] * 0.125f;
        Mst[tid] = NEGINF; Lst[tid] = 0.f;
    }
    int tx = tid & 15, ty = tid >> 4;
    float acc[2][4];
#pragma unroll
    for (int i = 0; i < 2; i++)
#pragma unroll
        for (int j = 0; j < 4; j++) acc[i][j] = 0.f;

    for (int kt = 0; kt < S; kt += 64) {
        __syncthreads();
        const float* Kg = Kb + (size_t)(b * S + kt) * H + h * HD;
        for (int i = tid; i < 1024; i += 256) {
            int r = i >> 4, c4 = (i & 15) * 4;
            float4 v = *(const float4*)(Kg + (size_t)r * H + c4);
            KV[c4 + 0][r] = v.x; KV[c4 + 1][r] = v.y;
            KV[c4 + 2][r] = v.z; KV[c4 + 3][r] = v.w;
        }
        if (tid < 64) Madd[tid] = (maskb[b * S + kt + tid] == 0) ? NEGINF : 0.f;
        __syncthreads();

        // scores: q = ty*2+{0,1}, k = tx*4+j
        float sc[2][4];
#pragma unroll
        for (int i = 0; i < 2; i++)
#pragma unroll
            for (int j = 0; j < 4; j++) sc[i][j] = 0.f;
#pragma unroll 16
        for (int d = 0; d < 64; d++) {
            float qv0 = QsT[d][ty * 2], qv1 = QsT[d][ty * 2 + 1];
            float4 kv = *(const float4*)&KV[d][tx * 4];
            sc[0][0] += qv0 * kv.x; sc[0][1] += qv0 * kv.y;
            sc[0][2] += qv0 * kv.z; sc[0][3] += qv0 * kv.w;
            sc[1][0] += qv1 * kv.x; sc[1][1] += qv1 * kv.y;
            sc[1][2] += qv1 * kv.z; sc[1][3] += qv1 * kv.w;
        }
#pragma unroll
        for (int i = 0; i < 2; i++) {
            float mm = Msc[ty * 2 + i];
#pragma unroll
            for (int j = 0; j < 4; j++)
                Ss[ty * 2 + i][tx * 4 + j] = sc[i][j] * mm + Madd[tx * 4 + j];
        }
        __syncthreads();

        // online softmax: warp handles 4 query rows
#pragma unroll
        for (int r = 0; r < 4; r++) {
            int q = warp * 4 + r;
            float s0 = Ss[q][lane], s1 = Ss[q][lane + 32];
            float mx = fmaxf(s0, s1);
#pragma unroll
            for (int o = 16; o > 0; o >>= 1)
                mx = fmaxf(mx, __shfl_xor_sync(0xffffffffu, mx, o));
            float mold = Mst[q];
            float mnew = fmaxf(mold, mx);
            float p0, p1, al;
            if (mnew == NEGINF) { p0 = 0.f; p1 = 0.f; al = 1.f; }
            else {
                p0 = __expf(s0 - mnew); p1 = __expf(s1 - mnew);
                al = (mold == NEGINF) ? 0.f : __expf(mold - mnew);
            }
            float ps = p0 + p1;
#pragma unroll
            for (int o = 16; o > 0; o >>= 1)
                ps += __shfl_xor_sync(0xffffffffu, ps, o);
            if (lane == 0) { Mst[q] = mnew; Lst[q] = Lst[q] * al + ps; Alp[q] = al; }
            Ps[lane][q] = p0; Ps[lane + 32][q] = p1;
        }
        __syncthreads();

        // load V into KV as [k][d]
        const float* Vg = Vb + (size_t)(b * S + kt) * H + h * HD;
        for (int i = tid; i < 1024; i += 256) {
            int r = i >> 4, c4 = (i & 15) * 4;
            *(float4*)&KV[r][c4] = *(const float4*)(Vg + (size_t)r * H + c4);
        }
        __syncthreads();

        float a0 = Alp[ty * 2], a1 = Alp[ty * 2 + 1];
#pragma unroll
        for (int j = 0; j < 4; j++) { acc[0][j] *= a0; acc[1][j] *= a1; }
#pragma unroll 16
        for (int k = 0; k < 64; k++) {
            float p0v = Ps[k][ty * 2], p1v = Ps[k][ty * 2 + 1];
            float4 vv = *(const float4*)&KV[k][tx * 4];
            acc[0][0] += p0v * vv.x; acc[0][1] += p0v * vv.y;
            acc[0][2] += p0v * vv.z; acc[0][3] += p0v * vv.w;
            acc[1][0] += p1v * vv.x; acc[1][1] += p1v * vv.y;
            acc[1][2] += p1v * vv.z; acc[1][3] += p1v * vv.w;
        }
    }
    __syncthreads();
    float* Og = Ob + (size_t)(b * S + q0) * H + h * HD;
#pragma unroll
    for (int i = 0; i < 2; i++) {
        float inv = 1.f / Lst[ty * 2 + i];
        float4 o;
        o.x = acc[i][0] * inv; o.y = acc[i][1] * inv;
        o.z = acc[i][2] * inv; o.w = acc[i][3] * inv;
        *(float4*)(Og + (size_t)(ty * 2 + i) * H + tx * 4) = o;
    }
}

// ---------------- big-head attention: 4 heads, hd=256 (causal & meta MHA) ----------------
__global__ __launch_bounds__(256) void attn_big(
    const float* __restrict__ Qb, const float* __restrict__ Kb,
    const float* __restrict__ Vb, int ld, float* __restrict__ Ob, float scale)
{
    __shared__ float QsT[256][16];    // Q transposed [d][q], full depth
    __shared__ float KV[64][64];      // K^T chunk [d][k] / V chunk [k][d]
    __shared__ float Ss[16][64];
    __shared__ float Ps[64][17];
    __shared__ float Mst[16], Lst[16], Alp[16];

    const float NEGINF = __int_as_float(0xff800000);
    int tid = threadIdx.x, lane = tid & 31, warp = tid >> 5;
    int qt = blockIdx.x, h = blockIdx.y, b = blockIdx.z;
    int q0 = qt * 16;

    const float* Qg = Qb + (size_t)(b * S + q0) * ld + h * BD;
    for (int i = tid; i < 1024; i += 256) {
        int q = i >> 6, c4 = (i & 63) * 4;
        float4 v = *(const float4*)(Qg + (size_t)q * ld + c4);
        QsT[c4 + 0][q] = v.x; QsT[c4 + 1][q] = v.y;
        QsT[c4 + 2][q] = v.z; QsT[c4 + 3][q] = v.w;
    }
    if (tid < 16) { Mst[tid] = NEGINF; Lst[tid] = 0.f; }

    int tx = tid & 15, ty = tid >> 4;   // score: q=ty, k=tx*4+j ; PV: q=ty, d=ch*64+tx*4+j
    float acc[4][4];
#pragma unroll
    for (int c = 0; c < 4; c++)
#pragma unroll
        for (int j = 0; j < 4; j++) acc[c][j] = 0.f;

    for (int kt = 0; kt < S; kt += 64) {
        float sc[4] = {0.f, 0.f, 0.f, 0.f};
        const float* Kg = Kb + (size_t)(b * S + kt) * ld + h * BD;
#pragma unroll
        for (int ch = 0; ch < 4; ch++) {
            __syncthreads();
            for (int i = tid; i < 1024; i += 256) {
                int r = i >> 4, c4 = (i & 15) * 4;
                float4 v = *(const float4*)(Kg + (size_t)r * ld + ch * 64 + c4);
                KV[c4 + 0][r] = v.x; KV[c4 + 1][r] = v.y;
                KV[c4 + 2][r] = v.z; KV[c4 + 3][r] = v.w;
            }
            __syncthreads();
#pragma unroll 16
            for (int d = 0; d < 64; d++) {
                float qv = QsT[ch * 64 + d][ty];
                float4 kv = *(const float4*)&KV[d][tx * 4];
                sc[0] += qv * kv.x; sc[1] += qv * kv.y;
                sc[2] += qv * kv.z; sc[3] += qv * kv.w;
            }
        }
#pragma unroll
        for (int j = 0; j < 4; j++) Ss[ty][tx * 4 + j] = sc[j] * scale;
        __syncthreads();

#pragma unroll
        for (int r = 0; r < 2; r++) {
            int q = warp * 2 + r;
            float s0 = Ss[q][lane], s1 = Ss[q][lane + 32];
            float mx = fmaxf(s0, s1);
#pragma unroll
            for (int o = 16; o > 0; o >>= 1)
                mx = fmaxf(mx, __shfl_xor_sync(0xffffffffu, mx, o));
            float mold = Mst[q];
            float mnew = fmaxf(mold, mx);
            float p0 = __expf(s0 - mnew), p1 = __expf(s1 - mnew);
            float al = (mold == NEGINF) ? 0.f : __expf(mold - mnew);
            float ps = p0 + p1;
#pragma unroll
            for (int o = 16; o > 0; o >>= 1)
                ps += __shfl_xor_sync(0xffffffffu, ps, o);
            if (lane == 0) { Mst[q] = mnew; Lst[q] = Lst[q] * al + ps; Alp[q] = al; }
            Ps[lane][q] = p0; Ps[lane + 32][q] = p1;
        }
        __syncthreads();

        float al = Alp[ty];
#pragma unroll
        for (int c = 0; c < 4; c++)
#pragma unroll
            for (int j = 0; j < 4; j++) acc[c][j] *= al;

        const float* Vg = Vb + (size_t)(b * S + kt) * ld + h * BD;
#pragma unroll
        for (int ch = 0; ch < 4; ch++) {
            __syncthreads();
            for (int i = tid; i < 1024; i += 256) {
                int r = i >> 4, c4 = (i & 15) * 4;
                *(float4*)&KV[r][c4] = *(const float4*)(Vg + (size_t)r * ld + ch * 64 + c4);
            }
            __syncthreads();
#pragma unroll 16
            for (int k = 0; k < 64; k++) {
                float pv = Ps[k][ty];
                float4 vv = *(const float4*)&KV[k][tx * 4];
                acc[ch][0] += pv * vv.x; acc[ch][1] += pv * vv.y;
                acc[ch][2] += pv * vv.z; acc[ch][3] += pv * vv.w;
            }
        }
    }
    __syncthreads();
    float inv = 1.f / Lst[ty];
    float* Og = Ob + (size_t)(b * S + q0 + ty) * H + h * BD;
#pragma unroll
    for (int ch = 0; ch < 4; ch++) {
        float4 o;
        o.x = acc[ch][0] * inv; o.y = acc[ch][1] * inv;
        o.z = acc[ch][2] * inv; o.w = acc[ch][3] * inv;
        *(float4*)(Og + ch * 64 + tx * 4) = o;
    }
}

// ---------------- elementwise blend: dst = a*wa + b*wb ----------------
__global__ __launch_bounds__(256) void blend(
    float* __restrict__ dst, const float* __restrict__ a,
    const float* __restrict__ bsrc, float wa, float wb, int n)
{
    int i = blockIdx.x * 256 + threadIdx.x;
    if (i < n) dst[i] = a[i] * wa + bsrc[i] * wb;
}

// ---------------- launch ----------------
extern "C" void kernel_launch(void* const* d_in, const int* in_sizes, int n_in,
                              void* d_out, int out_size)
{
    (void)in_sizes; (void)n_in; (void)out_size;
    const float* hs      = (const float*)d_in[0];
    const int*   mask    = (const int*)  d_in[1];
    const float* cvec    = (const float*)d_in[2];
    const float* Wq      = (const float*)d_in[3];
    const float* bq      = (const float*)d_in[4];
    const float* Wk      = (const float*)d_in[5];
    const float* bk      = (const float*)d_in[6];
    const float* Wv      = (const float*)d_in[7];
    const float* bv      = (const float*)d_in[8];
    const float* Wg      = (const float*)d_in[9];
    const float* bg      = (const float*)d_in[10];
    const float* Wa      = (const float*)d_in[11];
    const float* ba      = (const float*)d_in[12];
    const float* ca_in_w = (const float*)d_in[13];
    const float* ca_in_b = (const float*)d_in[14];
    const float* ca_ow   = (const float*)d_in[15];
    const float* ca_ob   = (const float*)d_in[16];
    const float* ma_in_w = (const float*)d_in[17];
    const float* ma_in_b = (const float*)d_in[18];
    const float* ma_ow   = (const float*)d_in[19];
    const float* ma_ob   = (const float*)d_in[20];
    const float* Wo      = (const float*)d_in[21];
    const float* bo      = (const float*)d_in[22];

    float *Q, *K, *V, *MOD, *CTX, *QKV3, *T1, *T2;
    cudaGetSymbolAddress((void**)&Q, g_Q);
    cudaGetSymbolAddress((void**)&K, g_K);
    cudaGetSymbolAddress((void**)&V, g_V);
    cudaGetSymbolAddress((void**)&MOD, g_MOD);
    cudaGetSymbolAddress((void**)&CTX, g_CTX);
    cudaGetSymbolAddress((void**)&QKV3, g_QKV3);
    cudaGetSymbolAddress((void**)&T1, g_T1);
    cudaGetSymbolAddress((void**)&T2, g_T2);

    dim3 gN1(H / 128, MS / 128);          // 8 x 32
    dim3 gN3(3 * H / 128, MS / 128);      // 24 x 32

    // main attention path
    gemm_tf32<<<gN1, 256>>>(hs, Wq, bq, Q, MS, H, H);
    gemm_tf32<<<gN1, 256>>>(hs, Wk, bk, K, MS, H, H);
    gemm_tf32<<<gN1, 256>>>(hs, Wv, bv, V, MS, H, H);
    gatemod<<<MS * NH / 256, 256>>>(hs, Wg, bg, cvec, Wa, ba, MOD);
    attn_main<<<dim3(S / 32, NH, B), 256>>>(Q, K, V, MOD, mask, CTX);

    // causal branch
    gemm_tf32<<<gN3, 256>>>(hs, ca_in_w, ca_in_b, QKV3, MS, 3 * H, H);
    attn_big<<<dim3(S / 16, BH, B), 256>>>(QKV3, QKV3 + H, QKV3 + 2 * H, 3 * H, T1, 0.0625f);
    gemm_tf32<<<gN1, 256>>>(T1, ca_ow, ca_ob, T2, MS, H, H);
    blend<<<MS * H / 256, 256>>>(CTX, CTX, T2, 0.3f, 0.7f, MS * H);

    // metacognitive branch
    gemm_tf32<<<gN3, 256>>>(CTX, ma_in_w, ma_in_b, QKV3, MS, 3 * H, H);
    attn_big<<<dim3(S / 16, BH, B), 256>>>(QKV3, QKV3 + H, QKV3 + 2 * H, 3 * H, T1, 0.0625f);
    gemm_tf32<<<gN1, 256>>>(T1, ma_ow, ma_ob, T2, MS, H, H);
    blend<<<MS * H / 256, 256>>>(CTX, CTX, T2, 0.85f, 0.15f, MS * H);

    // output projection
    gemm_tf32<<<gN1, 256>>>(CTX, Wo, bo, (float*)d_out, MS, H, H);
}

// round 3
// speedup vs baseline: 3.6700x; 3.2141x over previous
#include <cuda_runtime.h>
#include <math.h>

#define B 2
#define S 2048
#define H 1024
#define NH 16
#define HD 64
#define BH 4
#define BD 256
#define MS (B*S)   /* 4096 rows */

// ---------------- scratch (static device globals; no allocations) ----------------
__device__ float g_Q[MS * H];
__device__ float g_K[MS * H];
__device__ float g_V[MS * H];
__device__ float g_MOD[MS * NH];
__device__ float g_CTX[MS * H];
__device__ float g_QKV3[MS * 3 * H];
__device__ float g_T1[MS * H];
__device__ float g_T2[MS * H];

// ---------------- common MMA helpers ----------------
__device__ __forceinline__ unsigned f2tf32(float f) {
    unsigned u;
    asm("cvt.rna.tf32.f32 %0, %1;" : "=r"(u) : "f"(f));
    return u;
}

__device__ __forceinline__ void mma_tf32(float* d, const unsigned* a, const unsigned* b) {
    asm volatile(
        "mma.sync.aligned.m16n8k8.row.col.f32.tf32.tf32.f32 "
        "{%0,%1,%2,%3}, {%4,%5,%6,%7}, {%8,%9}, {%0,%1,%2,%3};"
        : "+f"(d[0]), "+f"(d[1]), "+f"(d[2]), "+f"(d[3])
        : "r"(a[0]), "r"(a[1]), "r"(a[2]), "r"(a[3]), "r"(b[0]), "r"(b[1]));
}

// ---------------- TF32 tensor-core GEMM: C = A[MxK] @ W[KxN] + bias[N] ----------------
#define BM 128
#define BN 128
#define BK 32

__global__ __launch_bounds__(256) void gemm_tf32(
    const float* __restrict__ A, const float* __restrict__ W,
    const float* __restrict__ bias, float* __restrict__ C,
    int M, int N, int K)
{
    __shared__ unsigned As[BM][BK + 4];
    __shared__ unsigned Bs[BK][BN + 4];

    int tid = threadIdx.x;
    int warp = tid >> 5, lane = tid & 31;
    int gid = lane >> 2, tig = lane & 3;
    int wm = (warp >> 2) * 64;
    int wn = (warp & 3) * 32;
    int m0 = blockIdx.y * BM, n0 = blockIdx.x * BN;

    float acc[4][4][4];
#pragma unroll
    for (int mt = 0; mt < 4; mt++)
#pragma unroll
        for (int nt = 0; nt < 4; nt++)
#pragma unroll
            for (int r = 0; r < 4; r++) acc[mt][nt][r] = 0.f;

    int aRow[4], aCol[4], bRow[4], bCol[4];
#pragma unroll
    for (int i = 0; i < 4; i++) {
        int fi = tid + 256 * i;
        aRow[i] = fi >> 3;  aCol[i] = (fi & 7) * 4;
        bRow[i] = fi >> 5;  bCol[i] = (fi & 31) * 4;
    }

    float4 aReg[4], bReg[4];
#pragma unroll
    for (int i = 0; i < 4; i++) {
        aReg[i] = *(const float4*)(A + (size_t)(m0 + aRow[i]) * K + aCol[i]);
        bReg[i] = *(const float4*)(W + (size_t)bRow[i] * N + n0 + bCol[i]);
    }
#pragma unroll
    for (int i = 0; i < 4; i++) {
        As[aRow[i]][aCol[i] + 0] = f2tf32(aReg[i].x);
        As[aRow[i]][aCol[i] + 1] = f2tf32(aReg[i].y);
        As[aRow[i]][aCol[i] + 2] = f2tf32(aReg[i].z);
        As[aRow[i]][aCol[i] + 3] = f2tf32(aReg[i].w);
        uint4 bu;
        bu.x = f2tf32(bReg[i].x); bu.y = f2tf32(bReg[i].y);
        bu.z = f2tf32(bReg[i].z); bu.w = f2tf32(bReg[i].w);
        *(uint4*)&Bs[bRow[i]][bCol[i]] = bu;
    }
    __syncthreads();

    int ntiles = K / BK;
    for (int kt = 0; kt < ntiles; kt++) {
        if (kt + 1 < ntiles) {
            int kb = (kt + 1) * BK;
#pragma unroll
            for (int i = 0; i < 4; i++) {
                aReg[i] = *(const float4*)(A + (size_t)(m0 + aRow[i]) * K + kb + aCol[i]);
                bReg[i] = *(const float4*)(W + (size_t)(kb + bRow[i]) * N + n0 + bCol[i]);
            }
        }
#pragma unroll
        for (int q = 0; q < 4; q++) {
            int kq = q * 8;
            unsigned af[4][4], bf[4][2];
#pragma unroll
            for (int mt = 0; mt < 4; mt++) {
                int r = wm + mt * 16 + gid;
                af[mt][0] = As[r][kq + tig];
                af[mt][1] = As[r + 8][kq + tig];
                af[mt][2] = As[r][kq + tig + 4];
                af[mt][3] = As[r + 8][kq + tig + 4];
            }
#pragma unroll
            for (int nt = 0; nt < 4; nt++) {
                int c = wn + nt * 8 + gid;
                bf[nt][0] = Bs[kq + tig][c];
                bf[nt][1] = Bs[kq + tig + 4][c];
            }
#pragma unroll
            for (int mt = 0; mt < 4; mt++)
#pragma unroll
                for (int nt = 0; nt < 4; nt++)
                    mma_tf32(acc[mt][nt], af[mt], bf[nt]);
        }
        __syncthreads();
        if (kt + 1 < ntiles) {
#pragma unroll
            for (int i = 0; i < 4; i++) {
                As[aRow[i]][aCol[i] + 0] = f2tf32(aReg[i].x);
                As[aRow[i]][aCol[i] + 1] = f2tf32(aReg[i].y);
                As[aRow[i]][aCol[i] + 2] = f2tf32(aReg[i].z);
                As[aRow[i]][aCol[i] + 3] = f2tf32(aReg[i].w);
                uint4 bu;
                bu.x = f2tf32(bReg[i].x); bu.y = f2tf32(bReg[i].y);
                bu.z = f2tf32(bReg[i].z); bu.w = f2tf32(bReg[i].w);
                *(uint4*)&Bs[bRow[i]][bCol[i]] = bu;
            }
            __syncthreads();
        }
    }

#pragma unroll
    for (int mt = 0; mt < 4; mt++) {
        int r0 = m0 + wm + mt * 16 + gid;
#pragma unroll
        for (int nt = 0; nt < 4; nt++) {
            int c = n0 + wn + nt * 8 + tig * 2;
            float b0v = bias[c], b1v = bias[c + 1];
            float2 v0, v1;
            v0.x = acc[mt][nt][0] + b0v; v0.y = acc[mt][nt][1] + b1v;
            v1.x = acc[mt][nt][2] + b0v; v1.y = acc[mt][nt][3] + b1v;
            *(float2*)(C + (size_t)r0 * N + c) = v0;
            *(float2*)(C + (size_t)(r0 + 8) * N + c) = v1;
        }
    }
}

// ---------------- modulation: sigmoid(hs@Wg + bg + cvec@Wa + ba) ----------------
__global__ __launch_bounds__(256) void gatemod(
    const float* __restrict__ hs, const float* __restrict__ Wg,
    const float* __restrict__ bg, const float* __restrict__ cvec,
    const float* __restrict__ Wa, const float* __restrict__ ba,
    float* __restrict__ MODo)
{
    int t = blockIdx.x * 256 + threadIdx.x;
    int m = t >> 4, n = t & 15;
    const float* row = hs + (size_t)m * H;
    float s = 0.f;
    for (int k = 0; k < H; k++) s += row[k] * Wg[k * NH + n];
    float aw = ba[n];
#pragma unroll
    for (int k = 0; k < 16; k++) aw += cvec[k] * Wa[k * 16 + n];
    float x = s + bg[n] + aw;
    MODo[t] = 1.f / (1.f + __expf(-x));
}

// ---------------- main attention (TC): 16 heads, hd=64, modulated, masked ----------------
// 128 queries/block, 8 warps x 16 rows each; key tile 32; flash-attention-2 online softmax
__global__ __launch_bounds__(256) void attn_main_tc(
    const float* __restrict__ Qb, const float* __restrict__ Kb,
    const float* __restrict__ Vb, const float* __restrict__ MODb,
    const int* __restrict__ maskb, float* __restrict__ Ob)
{
    __shared__ unsigned Ks[32][68];   // K tile [key][d] tf32 (stride 68: 4 mod 32 -> cf)
    __shared__ unsigned Vs[32][72];   // V tile [key][d] tf32 (stride 72: 8 mod 32 -> cf for [k][n])
    __shared__ unsigned Ps[128][36];  // P [q][key] tf32 per-warp private rows
    __shared__ float Madd[32];

    int tid = threadIdx.x, lane = tid & 31, warp = tid >> 5;
    int gid = lane >> 2, tig = lane & 3;
    int q0 = blockIdx.x * 128, h = blockIdx.y, b = blockIdx.z;
    int qw = q0 + warp * 16;

    // Q fragments in registers (row-major A-frags), 8 k-steps over d=64
    unsigned qf[8][4];
    const float* Qg = Qb + (size_t)(b * S + qw) * H + h * HD;
#pragma unroll
    for (int s = 0; s < 8; s++) {
        int d = s * 8;
        qf[s][0] = f2tf32(Qg[(size_t)gid * H + d + tig]);
        qf[s][1] = f2tf32(Qg[(size_t)(gid + 8) * H + d + tig]);
        qf[s][2] = f2tf32(Qg[(size_t)gid * H + d + tig + 4]);
        qf[s][3] = f2tf32(Qg[(size_t)(gid + 8) * H + d + tig + 4]);
    }
    float mod0 = MODb[(size_t)(b * S + qw + gid) * NH + h] * 0.125f;
    float mod1 = MODb[(size_t)(b * S + qw + gid + 8) * NH + h] * 0.125f;

    float m0 = -1e30f, m1 = -1e30f, l0 = 0.f, l1 = 0.f;
    float oacc[8][4];
#pragma unroll
    for (int nf = 0; nf < 8; nf++)
#pragma unroll
        for (int r = 0; r < 4; r++) oacc[nf][r] = 0.f;

    for (int kt = 0; kt < S; kt += 32) {
        __syncthreads();
        const float* Kg = Kb + (size_t)(b * S + kt) * H + h * HD;
        const float* Vg = Vb + (size_t)(b * S + kt) * H + h * HD;
#pragma unroll
        for (int it = 0; it < 2; it++) {
            int r = (tid >> 4) + it * 16, c = (tid & 15) * 4;
            float4 kv = *(const float4*)(Kg + (size_t)r * H + c);
            uint4 ku;
            ku.x = f2tf32(kv.x); ku.y = f2tf32(kv.y);
            ku.z = f2tf32(kv.z); ku.w = f2tf32(kv.w);
            *(uint4*)&Ks[r][c] = ku;
            float4 vv = *(const float4*)(Vg + (size_t)r * H + c);
            uint4 vu;
            vu.x = f2tf32(vv.x); vu.y = f2tf32(vv.y);
            vu.z = f2tf32(vv.z); vu.w = f2tf32(vv.w);
            *(uint4*)&Vs[r][c] = vu;
        }
        if (tid < 32) Madd[tid] = maskb[b * S + kt + tid] ? 0.f : -1e30f;
        __syncthreads();

        // scores: warp's 16 rows x 32 keys (4 n-frags), 8 k-steps
        float sc[4][4];
#pragma unroll
        for (int nf = 0; nf < 4; nf++)
#pragma unroll
            for (int r = 0; r < 4; r++) sc[nf][r] = 0.f;
#pragma unroll
        for (int s = 0; s < 8; s++) {
            int kd = s * 8;
#pragma unroll
            for (int nf = 0; nf < 4; nf++) {
                unsigned bf[2];
                bf[0] = Ks[nf * 8 + gid][kd + tig];
                bf[1] = Ks[nf * 8 + gid][kd + tig + 4];
                mma_tf32(sc[nf], qf[s], bf);
            }
        }

        // modulate + mask, then online softmax (rows quad-local)
        float mx0 = -1e30f, mx1 = -1e30f;
#pragma unroll
        for (int nf = 0; nf < 4; nf++) {
            float ma = Madd[nf * 8 + tig * 2], mb2 = Madd[nf * 8 + tig * 2 + 1];
            sc[nf][0] = sc[nf][0] * mod0 + ma;
            sc[nf][1] = sc[nf][1] * mod0 + mb2;
            sc[nf][2] = sc[nf][2] * mod1 + ma;
            sc[nf][3] = sc[nf][3] * mod1 + mb2;
            mx0 = fmaxf(mx0, fmaxf(sc[nf][0], sc[nf][1]));
            mx1 = fmaxf(mx1, fmaxf(sc[nf][2], sc[nf][3]));
        }
        mx0 = fmaxf(mx0, __shfl_xor_sync(0xffffffffu, mx0, 1));
        mx0 = fmaxf(mx0, __shfl_xor_sync(0xffffffffu, mx0, 2));
        mx1 = fmaxf(mx1, __shfl_xor_sync(0xffffffffu, mx1, 1));
        mx1 = fmaxf(mx1, __shfl_xor_sync(0xffffffffu, mx1, 2));
        float mn0 = fmaxf(m0, mx0), mn1 = fmaxf(m1, mx1);
        float al0 = __expf(m0 - mn0), al1 = __expf(m1 - mn1);
        float ps0 = 0.f, ps1 = 0.f;
#pragma unroll
        for (int nf = 0; nf < 4; nf++) {
            float p00 = __expf(sc[nf][0] - mn0), p01 = __expf(sc[nf][1] - mn0);
            float p10 = __expf(sc[nf][2] - mn1), p11 = __expf(sc[nf][3] - mn1);
            ps0 += p00 + p01; ps1 += p10 + p11;
            int c = nf * 8 + tig * 2;
            Ps[warp * 16 + gid][c] = f2tf32(p00);
            Ps[warp * 16 + gid][c + 1] = f2tf32(p01);
            Ps[warp * 16 + gid + 8][c] = f2tf32(p10);
            Ps[warp * 16 + gid + 8][c + 1] = f2tf32(p11);
        }
        ps0 += __shfl_xor_sync(0xffffffffu, ps0, 1);
        ps0 += __shfl_xor_sync(0xffffffffu, ps0, 2);
        ps1 += __shfl_xor_sync(0xffffffffu, ps1, 1);
        ps1 += __shfl_xor_sync(0xffffffffu, ps1, 2);
        l0 = l0 * al0 + ps0; l1 = l1 * al1 + ps1;
        m0 = mn0; m1 = mn1;
#pragma unroll
        for (int nf = 0; nf < 8; nf++) {
            oacc[nf][0] *= al0; oacc[nf][1] *= al0;
            oacc[nf][2] *= al1; oacc[nf][3] *= al1;
        }
        __syncwarp();

        // PV: k = 32 keys (4 steps), n = 64 d (8 n-frags)
#pragma unroll
        for (int s = 0; s < 4; s++) {
            int kk = s * 8;
            unsigned af[4];
            af[0] = Ps[warp * 16 + gid][kk + tig];
            af[1] = Ps[warp * 16 + gid + 8][kk + tig];
            af[2] = Ps[warp * 16 + gid][kk + tig + 4];
            af[3] = Ps[warp * 16 + gid + 8][kk + tig + 4];
#pragma unroll
            for (int nf = 0; nf < 8; nf++) {
                unsigned bf[2];
                bf[0] = Vs[kk + tig][nf * 8 + gid];
                bf[1] = Vs[kk + tig + 4][nf * 8 + gid];
                mma_tf32(oacc[nf], af, bf);
            }
        }
    }

    float inv0 = 1.f / l0, inv1 = 1.f / l1;
    float* Og = Ob + (size_t)(b * S + qw) * H + h * HD;
#pragma unroll
    for (int nf = 0; nf < 8; nf++) {
        int c = nf * 8 + tig * 2;
        float2 v0, v1;
        v0.x = oacc[nf][0] * inv0; v0.y = oacc[nf][1] * inv0;
        v1.x = oacc[nf][2] * inv1; v1.y = oacc[nf][3] * inv1;
        *(float2*)(Og + (size_t)gid * H + c) = v0;
        *(float2*)(Og + (size_t)(gid + 8) * H + c) = v1;
    }
}

// ---------------- big-head attention (TC): 4 heads, hd=256 ----------------
// 32 queries/block, warps 2(m) x 4(n); d chunked by 64 through one K/V buffer
__global__ __launch_bounds__(256) void attn_big_tc(
    const float* __restrict__ Qb, const float* __restrict__ Kb,
    const float* __restrict__ Vb, int ld, float* __restrict__ Ob, float scale)
{
    __shared__ unsigned Qs[32][260];   // full Q [q][256] tf32 (260: 4 mod 32 -> cf)
    __shared__ unsigned KVs[32][68];   // K or V chunk [row][64]
    __shared__ float SP[32][36];       // scores, then P (tf32 bits)
    __shared__ float Mst[32], Lst[32], Alp[32];

    int tid = threadIdx.x, lane = tid & 31, warp = tid >> 5;
    int gid = lane >> 2, tig = lane & 3;
    int wm = warp >> 2, wn = warp & 3;
    int q0 = blockIdx.x * 32, h = blockIdx.y, b = blockIdx.z;

    const float* Qg = Qb + (size_t)(b * S + q0) * ld + h * BD;
#pragma unroll
    for (int it = 0; it < 8; it++) {
        int idx = tid + it * 256;
        int r = idx >> 6, c = (idx & 63) * 4;
        float4 v = *(const float4*)(Qg + (size_t)r * ld + c);
        uint4 u;
        u.x = f2tf32(v.x); u.y = f2tf32(v.y); u.z = f2tf32(v.z); u.w = f2tf32(v.w);
        *(uint4*)&Qs[r][c] = u;
    }
    if (tid < 32) { Mst[tid] = -1e30f; Lst[tid] = 0.f; }

    float oacc[4][2][4];
#pragma unroll
    for (int ch = 0; ch < 4; ch++)
#pragma unroll
        for (int nf = 0; nf < 2; nf++)
#pragma unroll
            for (int r = 0; r < 4; r++) oacc[ch][nf][r] = 0.f;
    __syncthreads();

    unsigned* SPu = (unsigned*)&SP[0][0];

    for (int kt = 0; kt < S; kt += 32) {
        // ---- scores: 32q x 32k over d=256 in 4 chunks ----
        float sc[4] = {0.f, 0.f, 0.f, 0.f};
#pragma unroll
        for (int ch = 0; ch < 4; ch++) {
            __syncthreads();
            const float* Kg = Kb + (size_t)(b * S + kt) * ld + h * BD + ch * 64;
#pragma unroll
            for (int it = 0; it < 2; it++) {
                int idx = tid + it * 256;
                int r = idx >> 4, c = (idx & 15) * 4;
                float4 v = *(const float4*)(Kg + (size_t)r * ld + c);
                uint4 u;
                u.x = f2tf32(v.x); u.y = f2tf32(v.y); u.z = f2tf32(v.z); u.w = f2tf32(v.w);
                *(uint4*)&KVs[r][c] = u;
            }
            __syncthreads();
#pragma unroll
            for (int s = 0; s < 8; s++) {
                int dq = ch * 64 + s * 8;
                unsigned af[4], bf[2];
                af[0] = Qs[wm * 16 + gid][dq + tig];
                af[1] = Qs[wm * 16 + gid + 8][dq + tig];
                af[2] = Qs[wm * 16 + gid][dq + tig + 4];
                af[3] = Qs[wm * 16 + gid + 8][dq + tig + 4];
                bf[0] = KVs[wn * 8 + gid][s * 8 + tig];
                bf[1] = KVs[wn * 8 + gid][s * 8 + tig + 4];
                mma_tf32(sc, af, bf);
            }
        }
        {
            int c = wn * 8 + tig * 2;
            SP[wm * 16 + gid][c]     = sc[0] * scale;
            SP[wm * 16 + gid][c + 1] = sc[1] * scale;
            SP[wm * 16 + gid + 8][c]     = sc[2] * scale;
            SP[wm * 16 + gid + 8][c + 1] = sc[3] * scale;
        }
        __syncthreads();

        // ---- softmax: thread t handles row t>>3, 4 cols ----
        {
            int row = tid >> 3, c0 = (tid & 7) * 4;
            float4 sv = *(const float4*)&SP[row][c0];
            float mx = fmaxf(fmaxf(sv.x, sv.y), fmaxf(sv.z, sv.w));
            mx = fmaxf(mx, __shfl_xor_sync(0xffffffffu, mx, 1));
            mx = fmaxf(mx, __shfl_xor_sync(0xffffffffu, mx, 2));
            mx = fmaxf(mx, __shfl_xor_sync(0xffffffffu, mx, 4));
            float mold = Mst[row];
            float mnew = fmaxf(mold, mx);
            float p0 = __expf(sv.x - mnew), p1 = __expf(sv.y - mnew);
            float p2 = __expf(sv.z - mnew), p3 = __expf(sv.w - mnew);
            float ps = p0 + p1 + p2 + p3;
            ps += __shfl_xor_sync(0xffffffffu, ps, 1);
            ps += __shfl_xor_sync(0xffffffffu, ps, 2);
            ps += __shfl_xor_sync(0xffffffffu, ps, 4);
            if ((tid & 7) == 0) {
                float al = __expf(mold - mnew);
                Mst[row] = mnew; Lst[row] = Lst[row] * al + ps; Alp[row] = al;
            }
            uint4 pu;
            pu.x = f2tf32(p0); pu.y = f2tf32(p1); pu.z = f2tf32(p2); pu.w = f2tf32(p3);
            *(uint4*)&SP[row][c0] = pu;
        }
        __syncthreads();

        float al0 = Alp[wm * 16 + gid], al1 = Alp[wm * 16 + gid + 8];
#pragma unroll
        for (int ch = 0; ch < 4; ch++)
#pragma unroll
            for (int nf = 0; nf < 2; nf++) {
                oacc[ch][nf][0] *= al0; oacc[ch][nf][1] *= al0;
                oacc[ch][nf][2] *= al1; oacc[ch][nf][3] *= al1;
            }

        // ---- PV: warp (wm, wn) -> rows 16*wm, cols ch*64 + wn*16 + nf*8 ----
#pragma unroll
        for (int ch = 0; ch < 4; ch++) {
            __syncthreads();
            const float* Vg = Vb + (size_t)(b * S + kt) * ld + h * BD + ch * 64;
#pragma unroll
            for (int it = 0; it < 2; it++) {
                int idx = tid + it * 256;
                int r = idx >> 4, c = (idx & 15) * 4;
                float4 v = *(const float4*)(Vg + (size_t)r * ld + c);
                uint4 u;
                u.x = f2tf32(v.x); u.y = f2tf32(v.y); u.z = f2tf32(v.z); u.w = f2tf32(v.w);
                *(uint4*)&KVs[r][c] = u;
            }
            __syncthreads();
#pragma unroll
            for (int s = 0; s < 4; s++) {
                int kk = s * 8;
                unsigned af[4];
                af[0] = SPu[(size_t)(wm * 16 + gid) * 36 + kk + tig];
                af[1] = SPu[(size_t)(wm * 16 + gid + 8) * 36 + kk + tig];
                af[2] = SPu[(size_t)(wm * 16 + gid) * 36 + kk + tig + 4];
                af[3] = SPu[(size_t)(wm * 16 + gid + 8) * 36 + kk + tig + 4];
#pragma unroll
                for (int nf = 0; nf < 2; nf++) {
                    unsigned bf[2];
                    bf[0] = KVs[kk + tig][wn * 16 + nf * 8 + gid];
                    bf[1] = KVs[kk + tig + 4][wn * 16 + nf * 8 + gid];
                    mma_tf32(oacc[ch][nf], af, bf);
                }
            }
        }
    }
    __syncthreads();

    float inv0 = 1.f / Lst[wm * 16 + gid], inv1 = 1.f / Lst[wm * 16 + gid + 8];
    float* Og = Ob + (size_t)(b * S + q0 + wm * 16) * H + h * BD;
#pragma unroll
    for (int ch = 0; ch < 4; ch++)
#pragma unroll
        for (int nf = 0; nf < 2; nf++) {
            int c = ch * 64 + wn * 16 + nf * 8 + tig * 2;
            float2 v0, v1;
            v0.x = oacc[ch][nf][0] * inv0; v0.y = oacc[ch][nf][1] * inv0;
            v1.x = oacc[ch][nf][2] * inv1; v1.y = oacc[ch][nf][3] * inv1;
            *(float2*)(Og + (size_t)gid * H + c) = v0;
            *(float2*)(Og + (size_t)(gid + 8) * H + c) = v1;
        }
}

// ---------------- elementwise blend: dst = a*wa + b*wb ----------------
__global__ __launch_bounds__(256) void blend(
    float* __restrict__ dst, const float* __restrict__ a,
    const float* __restrict__ bsrc, float wa, float wb, int n)
{
    int i = blockIdx.x * 256 + threadIdx.x;
    if (i < n) dst[i] = a[i] * wa + bsrc[i] * wb;
}

// ---------------- launch ----------------
extern "C" void kernel_launch(void* const* d_in, const int* in_sizes, int n_in,
                              void* d_out, int out_size)
{
    (void)in_sizes; (void)n_in; (void)out_size;
    const float* hs      = (const float*)d_in[0];
    const int*   mask    = (const int*)  d_in[1];
    const float* cvec    = (const float*)d_in[2];
    const float* Wq      = (const float*)d_in[3];
    const float* bq      = (const float*)d_in[4];
    const float* Wk      = (const float*)d_in[5];
    const float* bk      = (const float*)d_in[6];
    const float* Wv      = (const float*)d_in[7];
    const float* bv      = (const float*)d_in[8];
    const float* Wg      = (const float*)d_in[9];
    const float* bg      = (const float*)d_in[10];
    const float* Wa      = (const float*)d_in[11];
    const float* ba      = (const float*)d_in[12];
    const float* ca_in_w = (const float*)d_in[13];
    const float* ca_in_b = (const float*)d_in[14];
    const float* ca_ow   = (const float*)d_in[15];
    const float* ca_ob   = (const float*)d_in[16];
    const float* ma_in_w = (const float*)d_in[17];
    const float* ma_in_b = (const float*)d_in[18];
    const float* ma_ow   = (const float*)d_in[19];
    const float* ma_ob   = (const float*)d_in[20];
    const float* Wo      = (const float*)d_in[21];
    const float* bo      = (const float*)d_in[22];

    float *Q, *K, *V, *MOD, *CTX, *QKV3, *T1, *T2;
    cudaGetSymbolAddress((void**)&Q, g_Q);
    cudaGetSymbolAddress((void**)&K, g_K);
    cudaGetSymbolAddress((void**)&V, g_V);
    cudaGetSymbolAddress((void**)&MOD, g_MOD);
    cudaGetSymbolAddress((void**)&CTX, g_CTX);
    cudaGetSymbolAddress((void**)&QKV3, g_QKV3);
    cudaGetSymbolAddress((void**)&T1, g_T1);
    cudaGetSymbolAddress((void**)&T2, g_T2);

    dim3 gN1(H / 128, MS / 128);
    dim3 gN3(3 * H / 128, MS / 128);

    // main attention path
    gemm_tf32<<<gN1, 256>>>(hs, Wq, bq, Q, MS, H, H);
    gemm_tf32<<<gN1, 256>>>(hs, Wk, bk, K, MS, H, H);
    gemm_tf32<<<gN1, 256>>>(hs, Wv, bv, V, MS, H, H);
    gatemod<<<MS * NH / 256, 256>>>(hs, Wg, bg, cvec, Wa, ba, MOD);
    attn_main_tc<<<dim3(S / 128, NH, B), 256>>>(Q, K, V, MOD, mask, CTX);

    // causal branch
    gemm_tf32<<<gN3, 256>>>(hs, ca_in_w, ca_in_b, QKV3, MS, 3 * H, H);
    attn_big_tc<<<dim3(S / 32, BH, B), 256>>>(QKV3, QKV3 + H, QKV3 + 2 * H, 3 * H, T1, 0.0625f);
    gemm_tf32<<<gN1, 256>>>(T1, ca_ow, ca_ob, T2, MS, H, H);
    blend<<<MS * H / 256, 256>>>(CTX, CTX, T2, 0.3f, 0.7f, MS * H);

    // metacognitive branch
    gemm_tf32<<<gN3, 256>>>(CTX, ma_in_w, ma_in_b, QKV3, MS, 3 * H, H);
    attn_big_tc<<<dim3(S / 32, BH, B), 256>>>(QKV3, QKV3 + H, QKV3 + 2 * H, 3 * H, T1, 0.0625f);
    gemm_tf32<<<gN1, 256>>>(T1, ma_ow, ma_ob, T2, MS, H, H);
    blend<<<MS * H / 256, 256>>>(CTX, CTX, T2, 0.85f, 0.15f, MS * H);

    // output projection
    gemm_tf32<<<gN1, 256>>>(CTX, Wo, bo, (float*)d_out, MS, H, H);
}

// round 5
// speedup vs baseline: 6.3810x; 1.7387x over previous
#include <cuda_runtime.h>
#include <cuda_fp16.h>
#include <stdint.h>
#include <math.h>

#define B 2
#define S 2048
#define H 1024
#define NH 16
#define HD 64
#define BH 4
#define BD 256
#define MS (B*S)   /* 4096 rows */

// ---------------- scratch (static device globals; no allocations) ----------------
__device__ float g_Q[MS * H];
__device__ float g_K[MS * H];
__device__ float g_V[MS * H];
__device__ float g_MOD[MS * NH];
__device__ float g_CTX[MS * H];
__device__ float g_QKV3[MS * 3 * H];
__device__ float g_T1[MS * H];
__device__ float g_T2[MS * H];

// ---------------- helpers ----------------
__device__ __forceinline__ uint32_t cvta_s(const void* p) {
    return (uint32_t)__cvta_generic_to_shared(p);
}
__device__ __forceinline__ uint32_t packh2(float a, float b) {
    __half2 h = __floats2half2_rn(a, b);
    return *reinterpret_cast<uint32_t*>(&h);
}
__device__ __forceinline__ void ldsm_x4(uint32_t addr, uint32_t* r) {
    asm volatile("ldmatrix.sync.aligned.m8n8.x4.shared.b16 {%0,%1,%2,%3}, [%4];"
        : "=r"(r[0]), "=r"(r[1]), "=r"(r[2]), "=r"(r[3]) : "r"(addr));
}
__device__ __forceinline__ void ldsm_x4_t(uint32_t addr, uint32_t* r) {
    asm volatile("ldmatrix.sync.aligned.m8n8.x4.trans.shared.b16 {%0,%1,%2,%3}, [%4];"
        : "=r"(r[0]), "=r"(r[1]), "=r"(r[2]), "=r"(r[3]) : "r"(addr));
}
__device__ __forceinline__ void ldsm_x2(uint32_t addr, uint32_t* r) {
    asm volatile("ldmatrix.sync.aligned.m8n8.x2.shared.b16 {%0,%1}, [%2];"
        : "=r"(r[0]), "=r"(r[1]) : "r"(addr));
}
__device__ __forceinline__ void mma_f16(float* d, const uint32_t* a, const uint32_t* b) {
    asm volatile(
        "mma.sync.aligned.m16n8k16.row.col.f32.f16.f16.f32 "
        "{%0,%1,%2,%3}, {%4,%5,%6,%7}, {%8,%9}, {%0,%1,%2,%3};"
        : "+f"(d[0]), "+f"(d[1]), "+f"(d[2]), "+f"(d[3])
        : "r"(a[0]), "r"(a[1]), "r"(a[2]), "r"(a[3]), "r"(b[0]), "r"(b[1]));
}

// ---------------- FP16 tensor-core GEMM: C = A[MxK] @ W[KxN] + bias[N] ----------------
// block 128x128x32, 8 warps 2x4, warp tile 64x32, mma m16n8k16, ldmatrix frags
__global__ __launch_bounds__(256) void gemm_f16(
    const float* __restrict__ A, const float* __restrict__ W,
    const float* __restrict__ bias, float* __restrict__ C,
    int M, int N, int K)
{
    __shared__ __half As[128][40];    // row stride 80B
    __shared__ __half Bs[32][136];    // row stride 272B

    int tid = threadIdx.x, warp = tid >> 5, lane = tid & 31;
    int wm = (warp >> 2) * 64, wn = (warp & 3) * 32;
    int m0 = blockIdx.y * 128, n0 = blockIdx.x * 128;
    int gid = lane >> 2, tig = lane & 3;

    float acc[4][4][4];
#pragma unroll
    for (int mt = 0; mt < 4; mt++)
#pragma unroll
        for (int nt = 0; nt < 4; nt++)
#pragma unroll
            for (int r = 0; r < 4; r++) acc[mt][nt][r] = 0.f;

    int aRow[4], aCol[4], bRow[4], bCol[4];
#pragma unroll
    for (int i = 0; i < 4; i++) {
        int fi = tid + 256 * i;
        aRow[i] = fi >> 3;  aCol[i] = (fi & 7) * 4;
        bRow[i] = fi >> 5;  bCol[i] = (fi & 31) * 4;
    }

    // ldmatrix lane addresses
    int lr = ((lane >> 3) & 1) * 8 + (lane & 7);
    int lc = (lane >> 4) * 8;
    uint32_t a_addr[4], b_addr[2];
#pragma unroll
    for (int mt = 0; mt < 4; mt++)
        a_addr[mt] = cvta_s(&As[wm + mt * 16 + lr][lc]);
#pragma unroll
    for (int ntp = 0; ntp < 2; ntp++)
        b_addr[ntp] = cvta_s(&Bs[lr][wn + ntp * 16 + lc]);

    uint2 aPk[4], bPk[4];
#pragma unroll
    for (int i = 0; i < 4; i++) {
        float4 av = *(const float4*)(A + (size_t)(m0 + aRow[i]) * K + aCol[i]);
        aPk[i].x = packh2(av.x, av.y); aPk[i].y = packh2(av.z, av.w);
        float4 bv = *(const float4*)(W + (size_t)bRow[i] * N + n0 + bCol[i]);
        bPk[i].x = packh2(bv.x, bv.y); bPk[i].y = packh2(bv.z, bv.w);
    }
#pragma unroll
    for (int i = 0; i < 4; i++) {
        *(uint2*)&As[aRow[i]][aCol[i]] = aPk[i];
        *(uint2*)&Bs[bRow[i]][bCol[i]] = bPk[i];
    }
    __syncthreads();

    int ntiles = K / 32;
    for (int kt = 0; kt < ntiles; kt++) {
        if (kt + 1 < ntiles) {
            int kb = (kt + 1) * 32;
#pragma unroll
            for (int i = 0; i < 4; i++) {
                float4 av = *(const float4*)(A + (size_t)(m0 + aRow[i]) * K + kb + aCol[i]);
                aPk[i].x = packh2(av.x, av.y); aPk[i].y = packh2(av.z, av.w);
                float4 bv = *(const float4*)(W + (size_t)(kb + bRow[i]) * N + n0 + bCol[i]);
                bPk[i].x = packh2(bv.x, bv.y); bPk[i].y = packh2(bv.z, bv.w);
            }
        }
#pragma unroll
        for (int q = 0; q < 2; q++) {
            int kq = q * 16;
            uint32_t af[4][4], bu0[4], bu1[4];
#pragma unroll
            for (int mt = 0; mt < 4; mt++) ldsm_x4(a_addr[mt] + kq * 2, af[mt]);
            ldsm_x4_t(b_addr[0] + kq * 272, bu0);
            ldsm_x4_t(b_addr[1] + kq * 272, bu1);
#pragma unroll
            for (int mt = 0; mt < 4; mt++) {
                mma_f16(acc[mt][0], af[mt], bu0 + 0);
                mma_f16(acc[mt][1], af[mt], bu0 + 2);
                mma_f16(acc[mt][2], af[mt], bu1 + 0);
                mma_f16(acc[mt][3], af[mt], bu1 + 2);
            }
        }
        __syncthreads();
        if (kt + 1 < ntiles) {
#pragma unroll
            for (int i = 0; i < 4; i++) {
                *(uint2*)&As[aRow[i]][aCol[i]] = aPk[i];
                *(uint2*)&Bs[bRow[i]][bCol[i]] = bPk[i];
            }
            __syncthreads();
        }
    }

#pragma unroll
    for (int mt = 0; mt < 4; mt++) {
        int r0 = m0 + wm + mt * 16 + gid;
#pragma unroll
        for (int nt = 0; nt < 4; nt++) {
            int c = n0 + wn + nt * 8 + tig * 2;
            float b0v = bias[c], b1v = bias[c + 1];
            float2 v0, v1;
            v0.x = acc[mt][nt][0] + b0v; v0.y = acc[mt][nt][1] + b1v;
            v1.x = acc[mt][nt][2] + b0v; v1.y = acc[mt][nt][3] + b1v;
            *(float2*)(C + (size_t)r0 * N + c) = v0;
            *(float2*)(C + (size_t)(r0 + 8) * N + c) = v1;
        }
    }
}

// ---------------- modulation: sigmoid(hs@Wg + bg + cvec@Wa + ba) ----------------
__global__ __launch_bounds__(256) void gatemod(
    const float* __restrict__ hs, const float* __restrict__ Wg,
    const float* __restrict__ bg, const float* __restrict__ cvec,
    const float* __restrict__ Wa, const float* __restrict__ ba,
    float* __restrict__ MODo)
{
    int t = blockIdx.x * 256 + threadIdx.x;
    int m = t >> 4, n = t & 15;
    const float* row = hs + (size_t)m * H;
    float s = 0.f;
#pragma unroll 4
    for (int k = 0; k < H; k++) s += row[k] * Wg[k * NH + n];
    float aw = ba[n];
#pragma unroll
    for (int k = 0; k < 16; k++) aw += cvec[k] * Wa[k * 16 + n];
    float x = s + bg[n] + aw;
    MODo[t] = 1.f / (1.f + __expf(-x));
}

// ---------------- main attention (fp16 TC): 16 heads, hd=64 ----------------
// 128 q/block, 8 warps x 16 rows; key tile 32; P stays in registers (C->A frag pack)
__global__ __launch_bounds__(256) void attn_main_f16(
    const float* __restrict__ Qb, const float* __restrict__ Kb,
    const float* __restrict__ Vb, const float* __restrict__ MODb,
    const int* __restrict__ maskb, float* __restrict__ Ob)
{
    __shared__ __half Ks[32][72];   // [key][d], 144B stride
    __shared__ __half Vs[32][72];   // [key][d]
    __shared__ float Madd[32];

    int tid = threadIdx.x, lane = tid & 31, warp = tid >> 5;
    int gid = lane >> 2, tig = lane & 3;
    int q0 = blockIdx.x * 128, h = blockIdx.y, b = blockIdx.z;
    int qw = q0 + warp * 16;

    // Q fragments in registers: 4 k-steps over d=64
    uint32_t qf[4][4];
    const float* Qg = Qb + (size_t)(b * S + qw) * H + h * HD;
#pragma unroll
    for (int s = 0; s < 4; s++) {
        int c0 = s * 16 + 2 * tig;
        float2 v;
        v = *(const float2*)(Qg + (size_t)gid * H + c0);          qf[s][0] = packh2(v.x, v.y);
        v = *(const float2*)(Qg + (size_t)(gid + 8) * H + c0);    qf[s][1] = packh2(v.x, v.y);
        v = *(const float2*)(Qg + (size_t)gid * H + c0 + 8);      qf[s][2] = packh2(v.x, v.y);
        v = *(const float2*)(Qg + (size_t)(gid + 8) * H + c0 + 8);qf[s][3] = packh2(v.x, v.y);
    }
    float mod0 = MODb[(size_t)(b * S + qw + gid) * NH + h] * 0.125f;
    float mod1 = MODb[(size_t)(b * S + qw + gid + 8) * NH + h] * 0.125f;

    // ldmatrix lane addrs
    uint32_t kaddr[2], vaddr[4];
#pragma unroll
    for (int ntp = 0; ntp < 2; ntp++)
        kaddr[ntp] = cvta_s(&Ks[(ntp * 2 + (lane >> 4)) * 8 + (lane & 7)][((lane >> 3) & 1) * 8]);
#pragma unroll
    for (int nfp = 0; nfp < 4; nfp++)
        vaddr[nfp] = cvta_s(&Vs[((lane >> 3) & 1) * 8 + (lane & 7)][(nfp * 2 + (lane >> 4)) * 8]);

    float m0v = -1e30f, m1v = -1e30f, l0 = 0.f, l1 = 0.f;
    float oacc[8][4];
#pragma unroll
    for (int nf = 0; nf < 8; nf++)
#pragma unroll
        for (int r = 0; r < 4; r++) oacc[nf][r] = 0.f;

    for (int kt = 0; kt < S; kt += 32) {
        __syncthreads();
        const float* Kg = Kb + (size_t)(b * S + kt) * H + h * HD;
        const float* Vg = Vb + (size_t)(b * S + kt) * H + h * HD;
#pragma unroll
        for (int it = 0; it < 2; it++) {
            int idx = tid + it * 256;
            int r = idx >> 4, c = (idx & 15) * 4;
            float4 kv = *(const float4*)(Kg + (size_t)r * H + c);
            uint2 ku; ku.x = packh2(kv.x, kv.y); ku.y = packh2(kv.z, kv.w);
            *(uint2*)&Ks[r][c] = ku;
            float4 vv = *(const float4*)(Vg + (size_t)r * H + c);
            uint2 vu; vu.x = packh2(vv.x, vv.y); vu.y = packh2(vv.z, vv.w);
            *(uint2*)&Vs[r][c] = vu;
        }
        if (tid < 32) Madd[tid] = maskb[b * S + kt + tid] ? 0.f : -1e30f;
        __syncthreads();

        // scores: 16 rows x 32 keys
        float sc[4][4];
#pragma unroll
        for (int nf = 0; nf < 4; nf++)
#pragma unroll
            for (int r = 0; r < 4; r++) sc[nf][r] = 0.f;
#pragma unroll
        for (int s = 0; s < 4; s++) {
            uint32_t ku0[4], ku1[4];
            ldsm_x4(kaddr[0] + s * 32, ku0);
            ldsm_x4(kaddr[1] + s * 32, ku1);
            mma_f16(sc[0], qf[s], ku0 + 0);
            mma_f16(sc[1], qf[s], ku0 + 2);
            mma_f16(sc[2], qf[s], ku1 + 0);
            mma_f16(sc[3], qf[s], ku1 + 2);
        }

        // modulate + mask + online softmax (quad-local rows)
        float mx0 = -1e30f, mx1 = -1e30f;
#pragma unroll
        for (int nf = 0; nf < 4; nf++) {
            float ma = Madd[nf * 8 + 2 * tig], mb2 = Madd[nf * 8 + 2 * tig + 1];
            sc[nf][0] = sc[nf][0] * mod0 + ma;
            sc[nf][1] = sc[nf][1] * mod0 + mb2;
            sc[nf][2] = sc[nf][2] * mod1 + ma;
            sc[nf][3] = sc[nf][3] * mod1 + mb2;
            mx0 = fmaxf(mx0, fmaxf(sc[nf][0], sc[nf][1]));
            mx1 = fmaxf(mx1, fmaxf(sc[nf][2], sc[nf][3]));
        }
        mx0 = fmaxf(mx0, __shfl_xor_sync(0xffffffffu, mx0, 1));
        mx0 = fmaxf(mx0, __shfl_xor_sync(0xffffffffu, mx0, 2));
        mx1 = fmaxf(mx1, __shfl_xor_sync(0xffffffffu, mx1, 1));
        mx1 = fmaxf(mx1, __shfl_xor_sync(0xffffffffu, mx1, 2));
        float mn0 = fmaxf(m0v, mx0), mn1 = fmaxf(m1v, mx1);
        float al0 = __expf(m0v - mn0), al1 = __expf(m1v - mn1);
        float ps0 = 0.f, ps1 = 0.f;
        uint32_t pva[2][4];
#pragma unroll
        for (int nf = 0; nf < 4; nf++) {
            float p00 = __expf(sc[nf][0] - mn0), p01 = __expf(sc[nf][1] - mn0);
            float p10 = __expf(sc[nf][2] - mn1), p11 = __expf(sc[nf][3] - mn1);
            ps0 += p00 + p01; ps1 += p10 + p11;
            int s2 = nf >> 1, hi = (nf & 1) * 2;
            pva[s2][hi]     = packh2(p00, p01);
            pva[s2][hi + 1] = packh2(p10, p11);
        }
        ps0 += __shfl_xor_sync(0xffffffffu, ps0, 1);
        ps0 += __shfl_xor_sync(0xffffffffu, ps0, 2);
        ps1 += __shfl_xor_sync(0xffffffffu, ps1, 1);
        ps1 += __shfl_xor_sync(0xffffffffu, ps1, 2);
        l0 = l0 * al0 + ps0; l1 = l1 * al1 + ps1;
        m0v = mn0; m1v = mn1;
#pragma unroll
        for (int nf = 0; nf < 8; nf++) {
            oacc[nf][0] *= al0; oacc[nf][1] *= al0;
            oacc[nf][2] *= al1; oacc[nf][3] *= al1;
        }

        // PV: P regs x V (ldsm trans)
#pragma unroll
        for (int s2 = 0; s2 < 2; s2++) {
#pragma unroll
            for (int nfp = 0; nfp < 4; nfp++) {
                uint32_t vu[4];
                ldsm_x4_t(vaddr[nfp] + s2 * 16 * 144, vu);
                mma_f16(oacc[nfp * 2],     pva[s2], vu + 0);
                mma_f16(oacc[nfp * 2 + 1], pva[s2], vu + 2);
            }
        }
    }

    float inv0 = 1.f / l0, inv1 = 1.f / l1;
    float* Og = Ob + (size_t)(b * S + qw) * H + h * HD;
#pragma unroll
    for (int nf = 0; nf < 8; nf++) {
        int c = nf * 8 + 2 * tig;
        float2 v0, v1;
        v0.x = oacc[nf][0] * inv0; v0.y = oacc[nf][1] * inv0;
        v1.x = oacc[nf][2] * inv1; v1.y = oacc[nf][3] * inv1;
        *(float2*)(Og + (size_t)gid * H + c) = v0;
        *(float2*)(Og + (size_t)(gid + 8) * H + c) = v1;
    }
}

// ---------------- big-head attention (fp16 TC): 4 heads, hd=256 ----------------
// 32 q/block, warps 2(m) x 4(n); Q in registers; full 32x256 K and V tiles in smem
__global__ __launch_bounds__(256) void attn_big_f16(
    const float* __restrict__ Qb, const float* __restrict__ Kb,
    const float* __restrict__ Vb, int ld, float* __restrict__ Ob, float scale)
{
    __shared__ __half Ks[32][264];   // [key][d], 528B stride
    __shared__ __half Vs[32][264];
    __shared__ float SP[32][36];     // scores
    __shared__ __half SPh[32][40];   // P (half)
    __shared__ float Mst[32], Lst[32], Alp[32];

    int tid = threadIdx.x, lane = tid & 31, warp = tid >> 5;
    int gid = lane >> 2, tig = lane & 3;
    int wm = warp >> 2, wn = warp & 3;
    int q0 = blockIdx.x * 32, h = blockIdx.y, b = blockIdx.z;

    // Q fragments in registers: 16 k-steps over d=256 (warp's 16 rows)
    uint32_t qf[16][4];
    const float* Qg = Qb + (size_t)(b * S + q0 + wm * 16) * ld + h * BD;
#pragma unroll
    for (int s = 0; s < 16; s++) {
        int c0 = s * 16 + 2 * tig;
        float2 v;
        v = *(const float2*)(Qg + (size_t)gid * ld + c0);          qf[s][0] = packh2(v.x, v.y);
        v = *(const float2*)(Qg + (size_t)(gid + 8) * ld + c0);    qf[s][1] = packh2(v.x, v.y);
        v = *(const float2*)(Qg + (size_t)gid * ld + c0 + 8);      qf[s][2] = packh2(v.x, v.y);
        v = *(const float2*)(Qg + (size_t)(gid + 8) * ld + c0 + 8);qf[s][3] = packh2(v.x, v.y);
    }
    if (tid < 32) { Mst[tid] = -1e30f; Lst[tid] = 0.f; }

    uint32_t kaddr = cvta_s(&Ks[wn * 8 + (lane & 7)][((lane >> 3) & 1) * 8]);
    uint32_t paddr = cvta_s(&SPh[wm * 16 + ((lane >> 3) & 1) * 8 + (lane & 7)][(lane >> 4) * 8]);
    uint32_t vaddr = cvta_s(&Vs[((lane >> 3) & 1) * 8 + (lane & 7)][wn * 64 + (lane >> 4) * 8]);

    float oacc[8][4];
#pragma unroll
    for (int nf = 0; nf < 8; nf++)
#pragma unroll
        for (int r = 0; r < 4; r++) oacc[nf][r] = 0.f;

    for (int kt = 0; kt < S; kt += 32) {
        __syncthreads();
        const float* Kg = Kb + (size_t)(b * S + kt) * ld + h * BD;
        const float* Vg = Vb + (size_t)(b * S + kt) * ld + h * BD;
#pragma unroll
        for (int it = 0; it < 8; it++) {
            int idx = tid + it * 256;
            int r = idx >> 6, c = (idx & 63) * 4;
            float4 kv = *(const float4*)(Kg + (size_t)r * ld + c);
            uint2 ku; ku.x = packh2(kv.x, kv.y); ku.y = packh2(kv.z, kv.w);
            *(uint2*)&Ks[r][c] = ku;
            float4 vv = *(const float4*)(Vg + (size_t)r * ld + c);
            uint2 vu; vu.x = packh2(vv.x, vv.y); vu.y = packh2(vv.z, vv.w);
            *(uint2*)&Vs[r][c] = vu;
        }
        __syncthreads();

        // scores: warp rows wm*16.., keys wn*8..+7, d=256 (16 k-steps)
        float sc[4] = {0.f, 0.f, 0.f, 0.f};
#pragma unroll
        for (int s = 0; s < 16; s++) {
            uint32_t ku[2];
            ldsm_x2(kaddr + s * 32, ku);
            mma_f16(sc, qf[s], ku);
        }
        {
            int rw = wm * 16 + gid, c = wn * 8 + 2 * tig;
            float2 v;
            v.x = sc[0] * scale; v.y = sc[1] * scale;
            *(float2*)&SP[rw][c] = v;
            v.x = sc[2] * scale; v.y = sc[3] * scale;
            *(float2*)&SP[rw + 8][c] = v;
        }
        __syncthreads();

        // softmax: thread handles row tid>>3, 4 cols
        {
            int row = tid >> 3, c0 = (tid & 7) * 4;
            float4 sv = *(const float4*)&SP[row][c0];
            float mx = fmaxf(fmaxf(sv.x, sv.y), fmaxf(sv.z, sv.w));
            mx = fmaxf(mx, __shfl_xor_sync(0xffffffffu, mx, 1));
            mx = fmaxf(mx, __shfl_xor_sync(0xffffffffu, mx, 2));
            mx = fmaxf(mx, __shfl_xor_sync(0xffffffffu, mx, 4));
            float mold = Mst[row];
            float mnew = fmaxf(mold, mx);
            float p0 = __expf(sv.x - mnew), p1 = __expf(sv.y - mnew);
            float p2 = __expf(sv.z - mnew), p3 = __expf(sv.w - mnew);
            float ps = p0 + p1 + p2 + p3;
            ps += __shfl_xor_sync(0xffffffffu, ps, 1);
            ps += __shfl_xor_sync(0xffffffffu, ps, 2);
            ps += __shfl_xor_sync(0xffffffffu, ps, 4);
            if ((tid & 7) == 0) {
                float al = __expf(mold - mnew);
                Mst[row] = mnew; Lst[row] = Lst[row] * al + ps; Alp[row] = al;
            }
            uint2 pu; pu.x = packh2(p0, p1); pu.y = packh2(p2, p3);
            *(uint2*)&SPh[row][c0] = pu;
        }
        __syncthreads();

        float al0 = Alp[wm * 16 + gid], al1 = Alp[wm * 16 + gid + 8];
#pragma unroll
        for (int nf = 0; nf < 8; nf++) {
            oacc[nf][0] *= al0; oacc[nf][1] *= al0;
            oacc[nf][2] *= al1; oacc[nf][3] *= al1;
        }

        // PV: rows wm*16.., cols wn*64..+63
#pragma unroll
        for (int s2 = 0; s2 < 2; s2++) {
            uint32_t pa[4];
            ldsm_x4(paddr + s2 * 32, pa);
#pragma unroll
            for (int nfp = 0; nfp < 4; nfp++) {
                uint32_t vu[4];
                ldsm_x4_t(vaddr + s2 * 8448 + nfp * 32, vu);
                mma_f16(oacc[nfp * 2],     pa, vu + 0);
                mma_f16(oacc[nfp * 2 + 1], pa, vu + 2);
            }
        }
    }

    float inv0 = 1.f / Lst[wm * 16 + gid], inv1 = 1.f / Lst[wm * 16 + gid + 8];
    float* Og = Ob + (size_t)(b * S + q0 + wm * 16) * H + h * BD;
#pragma unroll
    for (int nf = 0; nf < 8; nf++) {
        int c = wn * 64 + nf * 8 + 2 * tig;
        float2 v0, v1;
        v0.x = oacc[nf][0] * inv0; v0.y = oacc[nf][1] * inv0;
        v1.x = oacc[nf][2] * inv1; v1.y = oacc[nf][3] * inv1;
        *(float2*)(Og + (size_t)gid * H + c) = v0;
        *(float2*)(Og + (size_t)(gid + 8) * H + c) = v1;
    }
}

// ---------------- elementwise blend: dst = a*wa + b*wb ----------------
__global__ __launch_bounds__(256) void blend(
    float* __restrict__ dst, const float* __restrict__ a,
    const float* __restrict__ bsrc, float wa, float wb, int n)
{
    int i = blockIdx.x * 256 + threadIdx.x;
    if (i < n) dst[i] = a[i] * wa + bsrc[i] * wb;
}

// ---------------- launch ----------------
extern "C" void kernel_launch(void* const* d_in, const int* in_sizes, int n_in,
                              void* d_out, int out_size)
{
    (void)in_sizes; (void)n_in; (void)out_size;
    const float* hs      = (const float*)d_in[0];
    const int*   mask    = (const int*)  d_in[1];
    const float* cvec    = (const float*)d_in[2];
    const float* Wq      = (const float*)d_in[3];
    const float* bq      = (const float*)d_in[4];
    const float* Wk      = (const float*)d_in[5];
    const float* bk      = (const float*)d_in[6];
    const float* Wv      = (const float*)d_in[7];
    const float* bv      = (const float*)d_in[8];
    const float* Wg      = (const float*)d_in[9];
    const float* bg      = (const float*)d_in[10];
    const float* Wa      = (const float*)d_in[11];
    const float* ba      = (const float*)d_in[12];
    const float* ca_in_w = (const float*)d_in[13];
    const float* ca_in_b = (const float*)d_in[14];
    const float* ca_ow   = (const float*)d_in[15];
    const float* ca_ob   = (const float*)d_in[16];
    const float* ma_in_w = (const float*)d_in[17];
    const float* ma_in_b = (const float*)d_in[18];
    const float* ma_ow   = (const float*)d_in[19];
    const float* ma_ob   = (const float*)d_in[20];
    const float* Wo      = (const float*)d_in[21];
    const float* bo      = (const float*)d_in[22];

    float *Q, *K, *V, *MOD, *CTX, *QKV3, *T1, *T2;
    cudaGetSymbolAddress((void**)&Q, g_Q);
    cudaGetSymbolAddress((void**)&K, g_K);
    cudaGetSymbolAddress((void**)&V, g_V);
    cudaGetSymbolAddress((void**)&MOD, g_MOD);
    cudaGetSymbolAddress((void**)&CTX, g_CTX);
    cudaGetSymbolAddress((void**)&QKV3, g_QKV3);
    cudaGetSymbolAddress((void**)&T1, g_T1);
    cudaGetSymbolAddress((void**)&T2, g_T2);

    dim3 gN1(H / 128, MS / 128);
    dim3 gN3(3 * H / 128, MS / 128);

    // main attention path
    gemm_f16<<<gN1, 256>>>(hs, Wq, bq, Q, MS, H, H);
    gemm_f16<<<gN1, 256>>>(hs, Wk, bk, K, MS, H, H);
    gemm_f16<<<gN1, 256>>>(hs, Wv, bv, V, MS, H, H);
    gatemod<<<MS * NH / 256, 256>>>(hs, Wg, bg, cvec, Wa, ba, MOD);
    attn_main_f16<<<dim3(S / 128, NH, B), 256>>>(Q, K, V, MOD, mask, CTX);

    // causal branch
    gemm_f16<<<gN3, 256>>>(hs, ca_in_w, ca_in_b, QKV3, MS, 3 * H, H);
    attn_big_f16<<<dim3(S / 32, BH, B), 256>>>(QKV3, QKV3 + H, QKV3 + 2 * H, 3 * H, T1, 0.0625f);
    gemm_f16<<<gN1, 256>>>(T1, ca_ow, ca_ob, T2, MS, H, H);
    blend<<<MS * H / 256, 256>>>(CTX, CTX, T2, 0.3f, 0.7f, MS * H);

    // metacognitive branch
    gemm_f16<<<gN3, 256>>>(CTX, ma_in_w, ma_in_b, QKV3, MS, 3 * H, H);
    attn_big_f16<<<dim3(S / 32, BH, B), 256>>>(QKV3, QKV3 + H, QKV3 + 2 * H, 3 * H, T1, 0.0625f);
    gemm_f16<<<gN1, 256>>>(T1, ma_ow, ma_ob, T2, MS, H, H);
    blend<<<MS * H / 256, 256>>>(CTX, CTX, T2, 0.85f, 0.15f, MS * H);

    // output projection
    gemm_f16<<<gN1, 256>>>(CTX, Wo, bo, (float*)d_out, MS, H, H);
}